// round 5
// baseline (speedup 1.0000x reference)
#include <cuda_runtime.h>

#define N_NODES 50000
#define N_EDGES 1200000
#define N_REL   45
#define IN_C    64
#define HID_C   32
#define OUT_C   16

#define SCAT_EPB 2048   // edges per scatter block

// Packed fp32x2 helpers (sm_103a)
#define FMA2(acc, a, b) \
    asm("fma.rn.f32x2 %0, %1, %2, %0;" : "+l"(acc) : "l"(a), "l"(b))
#define ADD2(out, a, b) \
    asm("add.rn.f32x2 %0, %1, %2;" : "=l"(out) : "l"(a), "l"(b))
#define PACK2(out, lo, hi) \
    asm("mov.b64 %0, {%1, %2};" : "=l"(out) : "f"(lo), "f"(hi))
#define UNPACK2(lo, hi, in) \
    asm("mov.b64 {%0, %1}, %2;" : "=f"(lo), "=f"(hi) : "l"(in))

// Scratch (device globals: no allocation allowed in kernel_launch)
__device__ int   g_cnt[N_REL * N_NODES];   // per-(rel,dst) edge counts
__device__ int   g_hist[N_REL];            // per-relation edge counts
__device__ int   g_off[N_REL + 1];         // exclusive scan of g_hist
__device__ int   g_cursor[N_REL];          // scatter cursors
__device__ int   g_rel[N_EDGES];           // unsorted relation per edge
__device__ int   gs_src[N_EDGES];          // sorted-by-relation edge data
__device__ int   gs_dst[N_EDGES];
__device__ float gs_w[N_EDGES];
__device__ float g_h1[N_NODES * HID_C];    // layer-1 output (pre-ReLU)
__device__ float g_hr[N_NODES * HID_C];    // relu(h1)

// ---------------------------------------------------------------------------
__global__ void zero_kernel() {
    int i = blockIdx.x * blockDim.x + threadIdx.x;
    int stride = gridDim.x * blockDim.x;
    for (; i < N_REL * N_NODES; i += stride) g_cnt[i] = 0;
    if (blockIdx.x == 0 && threadIdx.x < N_REL) g_hist[threadIdx.x] = 0;
}

__global__ void count_kernel(const int* __restrict__ edge_index,
                             const int* __restrict__ edge_type) {
    __shared__ int sh[N_REL];
    if (threadIdx.x < N_REL) sh[threadIdx.x] = 0;
    __syncthreads();
    int e = blockIdx.x * blockDim.x + threadIdx.x;
    if (e < N_EDGES) {
        int dst = edge_index[N_EDGES + e];
        int rel = edge_type[e];
        g_rel[e] = rel;
        atomicAdd(&g_cnt[rel * N_NODES + dst], 1);
        atomicAdd(&sh[rel], 1);
    }
    __syncthreads();
    if (threadIdx.x < N_REL) atomicAdd(&g_hist[threadIdx.x], sh[threadIdx.x]);
}

__global__ void scan_kernel() {
    if (threadIdx.x == 0) {
        int acc = 0;
        for (int r = 0; r < N_REL; r++) {
            g_off[r] = acc;
            g_cursor[r] = acc;
            acc += g_hist[r];
        }
        g_off[N_REL] = acc;
    }
}

// Hierarchical-cursor relation sort; folds mean weight 1/cnt.
__global__ __launch_bounds__(256)
void scatter_kernel(const int* __restrict__ edge_index) {
    __shared__ int sh_cnt[N_REL];
    __shared__ int sh_base[N_REL];
    const int blockStart = blockIdx.x * SCAT_EPB;

    if (threadIdx.x < N_REL) sh_cnt[threadIdx.x] = 0;
    __syncthreads();

    for (int i = threadIdx.x; i < SCAT_EPB; i += blockDim.x) {
        int e = blockStart + i;
        if (e < N_EDGES) atomicAdd(&sh_cnt[g_rel[e]], 1);
    }
    __syncthreads();

    if (threadIdx.x < N_REL) {
        sh_base[threadIdx.x] = atomicAdd(&g_cursor[threadIdx.x], sh_cnt[threadIdx.x]);
        sh_cnt[threadIdx.x] = 0;
    }
    __syncthreads();

    for (int i = threadIdx.x; i < SCAT_EPB; i += blockDim.x) {
        int e = blockStart + i;
        if (e >= N_EDGES) continue;
        int rel = g_rel[e];
        int pos = sh_base[rel] + atomicAdd(&sh_cnt[rel], 1);
        int src = edge_index[e];
        int dst = edge_index[N_EDGES + e];
        int c   = g_cnt[rel * N_NODES + dst];
        gs_src[pos] = src;
        gs_dst[pos] = dst;
        gs_w[pos]   = 1.0f / (float)(c > 0 ? c : 1);
    }
}

// ---------------------------------------------------------------------------
// h1[n, c] = b1[c] + sum_i x[n, i] * root1[i, c]
__global__ void root1_kernel(const float* __restrict__ x,
                             const float* __restrict__ root,
                             const float* __restrict__ b) {
    int t = blockIdx.x * blockDim.x + threadIdx.x;
    if (t >= N_NODES * HID_C) return;
    int n = t >> 5;
    int c = t & 31;
    float acc = b[c];
    const float4* xr = (const float4*)(x + n * IN_C);
#pragma unroll
    for (int i4 = 0; i4 < IN_C / 4; i4++) {
        float4 xv = xr[i4];
        acc += xv.x * root[(i4 * 4 + 0) * HID_C + c];
        acc += xv.y * root[(i4 * 4 + 1) * HID_C + c];
        acc += xv.z * root[(i4 * 4 + 2) * HID_C + c];
        acc += xv.w * root[(i4 * 4 + 3) * HID_C + c];
    }
    g_h1[t] = acc;
}

// g_hr = relu(g_h1)  (after msg1 accumulation)
__global__ void relu_kernel() {
    int i = blockIdx.x * blockDim.x + threadIdx.x;
    if (i >= N_NODES * HID_C / 4) return;
    float4 v = ((const float4*)g_h1)[i];
    v.x = fmaxf(v.x, 0.0f); v.y = fmaxf(v.y, 0.0f);
    v.z = fmaxf(v.z, 0.0f); v.w = fmaxf(v.w, 0.0f);
    ((float4*)g_hr)[i] = v;
}

// out[n, c] = b2[c] + sum_i hr[n, i] * root2[i, c]
__global__ void root2_kernel(const float* __restrict__ root,
                             const float* __restrict__ b,
                             float* __restrict__ out) {
    int t = blockIdx.x * blockDim.x + threadIdx.x;
    if (t >= N_NODES * OUT_C) return;
    int n = t >> 4;
    int c = t & 15;
    float acc = b[c];
    const float4* hr = (const float4*)(g_hr + n * HID_C);
#pragma unroll
    for (int i4 = 0; i4 < HID_C / 4; i4++) {
        float4 hv = hr[i4];
        acc += hv.x * root[(i4 * 4 + 0) * OUT_C + c];
        acc += hv.y * root[(i4 * 4 + 1) * OUT_C + c];
        acc += hv.z * root[(i4 * 4 + 2) * OUT_C + c];
        acc += hv.w * root[(i4 * 4 + 3) * OUT_C + c];
    }
    out[t] = acc;
}

// ---------------------------------------------------------------------------
// Layer-1 messages over relation-sorted edges. blockIdx.x = relation.
// W packed f32x2 register-resident (lane = output channel).
__global__ __launch_bounds__(256, 2)
void msg1_kernel(const float* __restrict__ x, const float* __restrict__ W1) {
    const int r    = blockIdx.x;
    const int lane = threadIdx.x & 31;
    const int warp = threadIdx.x >> 5;

    // Wp[k] = packed (W[2k][lane], W[2k+1][lane])
    unsigned long long Wp[IN_C / 2];
    const float* Wr = W1 + r * IN_C * HID_C;
#pragma unroll
    for (int k = 0; k < IN_C / 2; k++) {
        float w0 = Wr[(2 * k) * HID_C + lane];
        float w1 = Wr[(2 * k + 1) * HID_C + lane];
        PACK2(Wp[k], w0, w1);
    }

    const int segStart = g_off[r];
    const int segEnd   = g_off[r + 1];
    const int wg = blockIdx.y * 8 + warp;
    const int nw = gridDim.y * 8;

    for (int base = segStart + wg * 32; base < segEnd; base += nw * 32) {
        int n = segEnd - base; if (n > 32) n = 32;
        int s32 = 0, d32 = 0; float w32 = 0.0f;
        if (lane < n) {
            s32 = gs_src[base + lane];
            d32 = gs_dst[base + lane];
            w32 = gs_w[base + lane];
        }
#pragma unroll 2
        for (int j = 0; j < n; j++) {
            int s = __shfl_sync(0xffffffffu, s32, j);
            int d = __shfl_sync(0xffffffffu, d32, j);
            float wj = __shfl_sync(0xffffffffu, w32, j);
            const ulonglong2* xr = (const ulonglong2*)(x + s * IN_C);
            unsigned long long a0 = 0ull, a1 = 0ull;
#pragma unroll 8
            for (int t = 0; t < IN_C / 4; t++) {   // 16 x 16B loads
                ulonglong2 xv = xr[t];
                FMA2(a0, xv.x, Wp[2 * t]);
                FMA2(a1, xv.y, Wp[2 * t + 1]);
            }
            unsigned long long a; ADD2(a, a0, a1);
            float lo, hi; UNPACK2(lo, hi, a);
            atomicAdd(&g_h1[d * HID_C + lane], (lo + hi) * wj);
        }
    }
}

// Layer-2 messages: half-warp per edge. c = lane&15 = output channel,
// half = lane>>4 selects which of 2 concurrent edges this lane serves.
__global__ __launch_bounds__(256, 2)
void msg2_kernel(const float* __restrict__ W2, float* __restrict__ out) {
    const int r    = blockIdx.x;
    const int lane = threadIdx.x & 31;
    const int warp = threadIdx.x >> 5;
    const int c    = lane & 15;
    const int half = lane >> 4;

    // Wp[k] = packed (W[2k][c], W[2k+1][c])
    unsigned long long Wp[HID_C / 2];
    const float* Wr = W2 + r * HID_C * OUT_C;
#pragma unroll
    for (int k = 0; k < HID_C / 2; k++) {
        float w0 = Wr[(2 * k) * OUT_C + c];
        float w1 = Wr[(2 * k + 1) * OUT_C + c];
        PACK2(Wp[k], w0, w1);
    }

    const int segStart = g_off[r];
    const int segEnd   = g_off[r + 1];
    const int wg = blockIdx.y * 8 + warp;
    const int nw = gridDim.y * 8;

    for (int base = segStart + wg * 32; base < segEnd; base += nw * 32) {
        int n = segEnd - base; if (n > 32) n = 32;
        int s32 = 0, d32 = 0; float w32 = 0.0f;
        if (lane < n) {
            s32 = gs_src[base + lane];
            d32 = gs_dst[base + lane];
            w32 = gs_w[base + lane];
        }
        int nPairs = (n + 1) >> 1;
        for (int jj = 0; jj < nPairs; jj++) {
            int ej = jj * 2 + half;
            bool act = ej < n;
            int sel = act ? ej : 0;
            int s = __shfl_sync(0xffffffffu, s32, sel);
            int d = __shfl_sync(0xffffffffu, d32, sel);
            float wj = __shfl_sync(0xffffffffu, w32, sel);
            const ulonglong2* hr = (const ulonglong2*)(g_hr + s * HID_C);
            unsigned long long a0 = 0ull, a1 = 0ull;
#pragma unroll
            for (int t = 0; t < HID_C / 4; t++) {  // 8 x 16B loads
                ulonglong2 hv = hr[t];
                FMA2(a0, hv.x, Wp[2 * t]);
                FMA2(a1, hv.y, Wp[2 * t + 1]);
            }
            unsigned long long a; ADD2(a, a0, a1);
            float lo, hi; UNPACK2(lo, hi, a);
            if (act) atomicAdd(&out[d * OUT_C + c], (lo + hi) * wj);
        }
    }
}

// ---------------------------------------------------------------------------
extern "C" void kernel_launch(void* const* d_in, const int* in_sizes, int n_in,
                              void* d_out, int out_size) {
    const float* x          = (const float*)d_in[0];
    const int*   edge_index = (const int*)d_in[1];
    const int*   edge_type  = (const int*)d_in[2];
    const float* W1         = (const float*)d_in[3];
    const float* root1      = (const float*)d_in[4];
    const float* b1         = (const float*)d_in[5];
    const float* W2         = (const float*)d_in[6];
    const float* root2      = (const float*)d_in[7];
    const float* b2         = (const float*)d_in[8];
    float*       out        = (float*)d_out;

    (void)in_sizes; (void)n_in; (void)out_size;

    zero_kernel<<<2048, 256>>>();
    count_kernel<<<(N_EDGES + 255) / 256, 256>>>(edge_index, edge_type);
    scan_kernel<<<1, 32>>>();
    scatter_kernel<<<(N_EDGES + SCAT_EPB - 1) / SCAT_EPB, 256>>>(edge_index);

    root1_kernel<<<(N_NODES * HID_C + 255) / 256, 256>>>(x, root1, b1);
    msg1_kernel<<<dim3(N_REL, 16), 256>>>(x, W1);
    relu_kernel<<<(N_NODES * HID_C / 4 + 255) / 256, 256>>>();

    root2_kernel<<<(N_NODES * OUT_C + 255) / 256, 256>>>(root2, b2, out);
    msg2_kernel<<<dim3(N_REL, 16), 256>>>(W2, out);
}

// round 6
// speedup vs baseline: 1.3288x; 1.3288x over previous
#include <cuda_runtime.h>

#define N_NODES 50000
#define N_EDGES 1200000
#define N_REL   45
#define IN_C    64
#define HID_C   32
#define OUT_C   16

#define SCAT_EPB 2048   // edges per scatter block

// Vector float2 global reduction (sm_90+)
#define RED2(ptr, v0, v1) \
    asm volatile("red.global.add.v2.f32 [%0], {%1, %2};" \
                 :: "l"(ptr), "f"(v0), "f"(v1) : "memory")

// Scratch (device globals: no allocation allowed in kernel_launch)
__device__ int   g_cnt[N_REL * N_NODES];   // per-(rel,dst) edge counts
__device__ int   g_hist[N_REL];            // per-relation edge counts
__device__ int   g_off[N_REL + 1];         // exclusive scan of g_hist
__device__ int   g_cursor[N_REL];          // scatter cursors
__device__ int   g_rel[N_EDGES];           // unsorted relation per edge
__device__ int   gs_src[N_EDGES];          // sorted-by-relation edge data
__device__ int   gs_dst[N_EDGES];
__device__ float gs_w[N_EDGES];
__device__ float g_h1[N_NODES * HID_C];    // layer-1 output (pre-ReLU)

// ---------------------------------------------------------------------------
__global__ void zero_kernel() {
    int i = blockIdx.x * blockDim.x + threadIdx.x;
    int stride = gridDim.x * blockDim.x;
    for (; i < N_REL * N_NODES; i += stride) g_cnt[i] = 0;
    if (blockIdx.x == 0 && threadIdx.x < N_REL) g_hist[threadIdx.x] = 0;
}

__global__ void count_kernel(const int* __restrict__ edge_index,
                             const int* __restrict__ edge_type) {
    __shared__ int sh[N_REL];
    if (threadIdx.x < N_REL) sh[threadIdx.x] = 0;
    __syncthreads();
    int e = blockIdx.x * blockDim.x + threadIdx.x;
    if (e < N_EDGES) {
        int dst = edge_index[N_EDGES + e];
        int rel = edge_type[e];
        g_rel[e] = rel;
        atomicAdd(&g_cnt[rel * N_NODES + dst], 1);
        atomicAdd(&sh[rel], 1);
    }
    __syncthreads();
    if (threadIdx.x < N_REL) atomicAdd(&g_hist[threadIdx.x], sh[threadIdx.x]);
}

__global__ void scan_kernel() {
    if (threadIdx.x == 0) {
        int acc = 0;
        for (int r = 0; r < N_REL; r++) {
            g_off[r] = acc;
            g_cursor[r] = acc;
            acc += g_hist[r];
        }
        g_off[N_REL] = acc;
    }
}

// Hierarchical-cursor relation sort; folds mean weight 1/cnt.
__global__ __launch_bounds__(256)
void scatter_kernel(const int* __restrict__ edge_index) {
    __shared__ int sh_cnt[N_REL];
    __shared__ int sh_base[N_REL];
    const int blockStart = blockIdx.x * SCAT_EPB;

    if (threadIdx.x < N_REL) sh_cnt[threadIdx.x] = 0;
    __syncthreads();

    for (int i = threadIdx.x; i < SCAT_EPB; i += blockDim.x) {
        int e = blockStart + i;
        if (e < N_EDGES) atomicAdd(&sh_cnt[g_rel[e]], 1);
    }
    __syncthreads();

    if (threadIdx.x < N_REL) {
        sh_base[threadIdx.x] = atomicAdd(&g_cursor[threadIdx.x], sh_cnt[threadIdx.x]);
        sh_cnt[threadIdx.x] = 0;
    }
    __syncthreads();

    for (int i = threadIdx.x; i < SCAT_EPB; i += blockDim.x) {
        int e = blockStart + i;
        if (e >= N_EDGES) continue;
        int rel = g_rel[e];
        int pos = sh_base[rel] + atomicAdd(&sh_cnt[rel], 1);
        int src = edge_index[e];
        int dst = edge_index[N_EDGES + e];
        int c   = g_cnt[rel * N_NODES + dst];
        gs_src[pos] = src;
        gs_dst[pos] = dst;
        gs_w[pos]   = 1.0f / (float)(c > 0 ? c : 1);
    }
}

// ---------------------------------------------------------------------------
// h1[n, c] = b1[c] + sum_i x[n, i] * root1[i, c]
__global__ void root1_kernel(const float* __restrict__ x,
                             const float* __restrict__ root,
                             const float* __restrict__ b) {
    int t = blockIdx.x * blockDim.x + threadIdx.x;
    if (t >= N_NODES * HID_C) return;
    int n = t >> 5;
    int c = t & 31;
    float acc = b[c];
    const float4* xr = (const float4*)(x + n * IN_C);
#pragma unroll
    for (int i4 = 0; i4 < IN_C / 4; i4++) {
        float4 xv = xr[i4];
        acc += xv.x * root[(i4 * 4 + 0) * HID_C + c];
        acc += xv.y * root[(i4 * 4 + 1) * HID_C + c];
        acc += xv.z * root[(i4 * 4 + 2) * HID_C + c];
        acc += xv.w * root[(i4 * 4 + 3) * HID_C + c];
    }
    g_h1[t] = acc;
}

// out[n, c] = b2[c] + sum_i relu(h1[n, i]) * root2[i, c]
__global__ void root2_kernel(const float* __restrict__ root,
                             const float* __restrict__ b,
                             float* __restrict__ out) {
    int t = blockIdx.x * blockDim.x + threadIdx.x;
    if (t >= N_NODES * OUT_C) return;
    int n = t >> 4;
    int c = t & 15;
    float acc = b[c];
    const float4* hr = (const float4*)(g_h1 + n * HID_C);
#pragma unroll
    for (int i4 = 0; i4 < HID_C / 4; i4++) {
        float4 hv = hr[i4];
        acc += fmaxf(hv.x, 0.0f) * root[(i4 * 4 + 0) * OUT_C + c];
        acc += fmaxf(hv.y, 0.0f) * root[(i4 * 4 + 1) * OUT_C + c];
        acc += fmaxf(hv.z, 0.0f) * root[(i4 * 4 + 2) * OUT_C + c];
        acc += fmaxf(hv.w, 0.0f) * root[(i4 * 4 + 3) * OUT_C + c];
    }
    out[t] = acc;
}

// ---------------------------------------------------------------------------
// Layer-1 messages over relation-sorted edges. blockIdx.x = relation.
// W column register-resident (lane = output channel). Scalar FFMA (round-4
// form; f32x2 packing regressed). Scatter uses v2 vector RED: adjacent
// channel pair combined via one shfl, even lanes issue red.global.add.v2.f32.
__global__ __launch_bounds__(256, 2)
void msg1_kernel(const float* __restrict__ x, const float* __restrict__ W1) {
    const int r    = blockIdx.x;
    const int lane = threadIdx.x & 31;
    const int warp = threadIdx.x >> 5;

    float Wreg[IN_C];
    const float* Wr = W1 + r * IN_C * HID_C;
#pragma unroll
    for (int i = 0; i < IN_C; i++) Wreg[i] = Wr[i * HID_C + lane];

    const int segStart = g_off[r];
    const int segEnd   = g_off[r + 1];
    const int wg = blockIdx.y * 8 + warp;
    const int nw = gridDim.y * 8;

    for (int base = segStart + wg * 32; base < segEnd; base += nw * 32) {
        int n = segEnd - base; if (n > 32) n = 32;
        int s32 = 0, d32 = 0; float w32 = 0.0f;
        if (lane < n) {
            s32 = gs_src[base + lane];
            d32 = gs_dst[base + lane];
            w32 = gs_w[base + lane];
        }
#pragma unroll 4
        for (int j = 0; j < n; j++) {
            int s = __shfl_sync(0xffffffffu, s32, j);
            int d = __shfl_sync(0xffffffffu, d32, j);
            float wj = __shfl_sync(0xffffffffu, w32, j);
            const float4* xr = (const float4*)(x + s * IN_C);
            float acc = 0.0f;
#pragma unroll
            for (int i4 = 0; i4 < IN_C / 4; i4++) {
                float4 xv = xr[i4];
                acc += xv.x * Wreg[i4 * 4 + 0];
                acc += xv.y * Wreg[i4 * 4 + 1];
                acc += xv.z * Wreg[i4 * 4 + 2];
                acc += xv.w * Wreg[i4 * 4 + 3];
            }
            float v0 = acc * wj;
            float v1 = __shfl_down_sync(0xffffffffu, v0, 1);
            if ((lane & 1) == 0)
                RED2(&g_h1[d * HID_C + lane], v0, v1);
        }
    }
}

// Layer-2 messages: input = relu(h1). c = lane&15 (output channel),
// half = lane>>4 splits the 32-dim reduction; combined via shfl.
// Final scatter via v2 vector RED from even lanes < 16.
__global__ __launch_bounds__(256, 2)
void msg2_kernel(const float* __restrict__ W2, float* __restrict__ out) {
    const int r    = blockIdx.x;
    const int lane = threadIdx.x & 31;
    const int warp = threadIdx.x >> 5;
    const int c    = lane & 15;
    const int half = lane >> 4;

    float Wreg[16];
    const float* Wr = W2 + r * HID_C * OUT_C;
#pragma unroll
    for (int k = 0; k < 16; k++) Wreg[k] = Wr[(half * 16 + k) * OUT_C + c];

    const int segStart = g_off[r];
    const int segEnd   = g_off[r + 1];
    const int wg = blockIdx.y * 8 + warp;
    const int nw = gridDim.y * 8;

    for (int base = segStart + wg * 32; base < segEnd; base += nw * 32) {
        int n = segEnd - base; if (n > 32) n = 32;
        int s32 = 0, d32 = 0; float w32 = 0.0f;
        if (lane < n) {
            s32 = gs_src[base + lane];
            d32 = gs_dst[base + lane];
            w32 = gs_w[base + lane];
        }
        for (int j = 0; j < n; j++) {
            int s = __shfl_sync(0xffffffffu, s32, j);
            int d = __shfl_sync(0xffffffffu, d32, j);
            float wj = __shfl_sync(0xffffffffu, w32, j);
            const float4* hr = (const float4*)(g_h1 + s * HID_C + half * 16);
            float acc = 0.0f;
#pragma unroll
            for (int k4 = 0; k4 < 4; k4++) {
                float4 hv = hr[k4];
                acc += fmaxf(hv.x, 0.0f) * Wreg[k4 * 4 + 0];
                acc += fmaxf(hv.y, 0.0f) * Wreg[k4 * 4 + 1];
                acc += fmaxf(hv.z, 0.0f) * Wreg[k4 * 4 + 2];
                acc += fmaxf(hv.w, 0.0f) * Wreg[k4 * 4 + 3];
            }
            acc += __shfl_down_sync(0xffffffffu, acc, 16);
            float v0 = acc * wj;
            float v1 = __shfl_down_sync(0xffffffffu, v0, 1);
            if (lane < 16 && (lane & 1) == 0)
                RED2(&out[d * OUT_C + c], v0, v1);
        }
    }
}

// ---------------------------------------------------------------------------
extern "C" void kernel_launch(void* const* d_in, const int* in_sizes, int n_in,
                              void* d_out, int out_size) {
    const float* x          = (const float*)d_in[0];
    const int*   edge_index = (const int*)d_in[1];
    const int*   edge_type  = (const int*)d_in[2];
    const float* W1         = (const float*)d_in[3];
    const float* root1      = (const float*)d_in[4];
    const float* b1         = (const float*)d_in[5];
    const float* W2         = (const float*)d_in[6];
    const float* root2      = (const float*)d_in[7];
    const float* b2         = (const float*)d_in[8];
    float*       out        = (float*)d_out;

    (void)in_sizes; (void)n_in; (void)out_size;

    zero_kernel<<<2048, 256>>>();
    count_kernel<<<(N_EDGES + 255) / 256, 256>>>(edge_index, edge_type);
    scan_kernel<<<1, 32>>>();
    scatter_kernel<<<(N_EDGES + SCAT_EPB - 1) / SCAT_EPB, 256>>>(edge_index);

    root1_kernel<<<(N_NODES * HID_C + 255) / 256, 256>>>(x, root1, b1);
    msg1_kernel<<<dim3(N_REL, 16), 256>>>(x, W1);

    root2_kernel<<<(N_NODES * OUT_C + 255) / 256, 256>>>(root2, b2, out);
    msg2_kernel<<<dim3(N_REL, 16), 256>>>(W2, out);
}

// round 7
// speedup vs baseline: 1.4992x; 1.1282x over previous
#include <cuda_runtime.h>

#define N_NODES 50000
#define N_EDGES 1200000
#define N_REL   45
#define IN_C    64
#define HID_C   32
#define OUT_C   16

#define SCAT_EPB 2048   // edges per scatter block

// Scratch (device globals: no allocation allowed in kernel_launch)
__device__ int   g_cnt[N_REL * N_NODES];   // per-(rel,dst) edge counts
__device__ int   g_hist[N_REL];            // per-relation edge counts
__device__ int   g_off[N_REL + 1];         // exclusive scan of g_hist
__device__ int   g_cursor[N_REL];          // scatter cursors
__device__ int   g_rel[N_EDGES];           // unsorted relation per edge
__device__ int   gs_src[N_EDGES];          // sorted-by-relation edge data
__device__ int   gs_dst[N_EDGES];
__device__ float gs_w[N_EDGES];
__device__ float g_h1[N_NODES * HID_C];    // layer-1 output (pre-ReLU)

// ---------------------------------------------------------------------------
__global__ void zero_kernel() {
    int i = blockIdx.x * blockDim.x + threadIdx.x;
    int stride = gridDim.x * blockDim.x;
    for (; i < N_REL * N_NODES; i += stride) g_cnt[i] = 0;
    if (blockIdx.x == 0 && threadIdx.x < N_REL) g_hist[threadIdx.x] = 0;
}

__global__ void count_kernel(const int* __restrict__ edge_index,
                             const int* __restrict__ edge_type) {
    __shared__ int sh[N_REL];
    if (threadIdx.x < N_REL) sh[threadIdx.x] = 0;
    __syncthreads();
    int e = blockIdx.x * blockDim.x + threadIdx.x;
    if (e < N_EDGES) {
        int dst = edge_index[N_EDGES + e];
        int rel = edge_type[e];
        g_rel[e] = rel;
        atomicAdd(&g_cnt[rel * N_NODES + dst], 1);
        atomicAdd(&sh[rel], 1);
    }
    __syncthreads();
    if (threadIdx.x < N_REL) atomicAdd(&g_hist[threadIdx.x], sh[threadIdx.x]);
}

__global__ void scan_kernel() {
    if (threadIdx.x == 0) {
        int acc = 0;
        for (int r = 0; r < N_REL; r++) {
            g_off[r] = acc;
            g_cursor[r] = acc;
            acc += g_hist[r];
        }
        g_off[N_REL] = acc;
    }
}

// Hierarchical-cursor relation sort; folds mean weight 1/cnt.
__global__ __launch_bounds__(256)
void scatter_kernel(const int* __restrict__ edge_index) {
    __shared__ int sh_cnt[N_REL];
    __shared__ int sh_base[N_REL];
    const int blockStart = blockIdx.x * SCAT_EPB;

    if (threadIdx.x < N_REL) sh_cnt[threadIdx.x] = 0;
    __syncthreads();

    for (int i = threadIdx.x; i < SCAT_EPB; i += blockDim.x) {
        int e = blockStart + i;
        if (e < N_EDGES) atomicAdd(&sh_cnt[g_rel[e]], 1);
    }
    __syncthreads();

    if (threadIdx.x < N_REL) {
        sh_base[threadIdx.x] = atomicAdd(&g_cursor[threadIdx.x], sh_cnt[threadIdx.x]);
        sh_cnt[threadIdx.x] = 0;
    }
    __syncthreads();

    for (int i = threadIdx.x; i < SCAT_EPB; i += blockDim.x) {
        int e = blockStart + i;
        if (e >= N_EDGES) continue;
        int rel = g_rel[e];
        int pos = sh_base[rel] + atomicAdd(&sh_cnt[rel], 1);
        int src = edge_index[e];
        int dst = edge_index[N_EDGES + e];
        int c   = g_cnt[rel * N_NODES + dst];
        gs_src[pos] = src;
        gs_dst[pos] = dst;
        gs_w[pos]   = 1.0f / (float)(c > 0 ? c : 1);
    }
}

// ---------------------------------------------------------------------------
// h1[n, c] = b1[c] + sum_i x[n, i] * root1[i, c]
__global__ void root1_kernel(const float* __restrict__ x,
                             const float* __restrict__ root,
                             const float* __restrict__ b) {
    int t = blockIdx.x * blockDim.x + threadIdx.x;
    if (t >= N_NODES * HID_C) return;
    int n = t >> 5;
    int c = t & 31;
    float acc = b[c];
    const float4* xr = (const float4*)(x + n * IN_C);
#pragma unroll
    for (int i4 = 0; i4 < IN_C / 4; i4++) {
        float4 xv = xr[i4];
        acc += xv.x * root[(i4 * 4 + 0) * HID_C + c];
        acc += xv.y * root[(i4 * 4 + 1) * HID_C + c];
        acc += xv.z * root[(i4 * 4 + 2) * HID_C + c];
        acc += xv.w * root[(i4 * 4 + 3) * HID_C + c];
    }
    g_h1[t] = acc;
}

// out[n, c] = b2[c] + sum_i relu(h1[n, i]) * root2[i, c]
__global__ void root2_kernel(const float* __restrict__ root,
                             const float* __restrict__ b,
                             float* __restrict__ out) {
    int t = blockIdx.x * blockDim.x + threadIdx.x;
    if (t >= N_NODES * OUT_C) return;
    int n = t >> 4;
    int c = t & 15;
    float acc = b[c];
    const float4* hr = (const float4*)(g_h1 + n * HID_C);
#pragma unroll
    for (int i4 = 0; i4 < HID_C / 4; i4++) {
        float4 hv = hr[i4];
        acc += fmaxf(hv.x, 0.0f) * root[(i4 * 4 + 0) * OUT_C + c];
        acc += fmaxf(hv.y, 0.0f) * root[(i4 * 4 + 1) * OUT_C + c];
        acc += fmaxf(hv.z, 0.0f) * root[(i4 * 4 + 2) * OUT_C + c];
        acc += fmaxf(hv.w, 0.0f) * root[(i4 * 4 + 3) * OUT_C + c];
    }
    out[t] = acc;
}

// ---------------------------------------------------------------------------
// Layer-1 messages over relation-sorted edges. blockIdx.x = relation.
// W column register-resident (lane = output channel). 512-thread blocks,
// grid (45, 6) = 270 blocks -> exactly one wave on 148 SMs at 1 block/SM.
__global__ __launch_bounds__(512, 1)
void msg1_kernel(const float* __restrict__ x, const float* __restrict__ W1) {
    const int r    = blockIdx.x;
    const int lane = threadIdx.x & 31;
    const int warp = threadIdx.x >> 5;   // 0..15

    float Wreg[IN_C];
    const float* Wr = W1 + r * IN_C * HID_C;
#pragma unroll
    for (int i = 0; i < IN_C; i++) Wreg[i] = Wr[i * HID_C + lane];

    const int segStart = g_off[r];
    const int segEnd   = g_off[r + 1];
    const int wg = blockIdx.y * 16 + warp;
    const int nw = gridDim.y * 16;

    for (int base = segStart + wg * 32; base < segEnd; base += nw * 32) {
        int n = segEnd - base; if (n > 32) n = 32;
        int s32 = 0, d32 = 0; float w32 = 0.0f;
        if (lane < n) {
            s32 = gs_src[base + lane];
            d32 = gs_dst[base + lane];
            w32 = gs_w[base + lane];
        }
#pragma unroll 4
        for (int j = 0; j < n; j++) {
            int s = __shfl_sync(0xffffffffu, s32, j);
            int d = __shfl_sync(0xffffffffu, d32, j);
            float wj = __shfl_sync(0xffffffffu, w32, j);
            const float4* xr = (const float4*)(x + s * IN_C);
            float acc = 0.0f;
#pragma unroll
            for (int i4 = 0; i4 < IN_C / 4; i4++) {
                float4 xv = xr[i4];
                acc += xv.x * Wreg[i4 * 4 + 0];
                acc += xv.y * Wreg[i4 * 4 + 1];
                acc += xv.z * Wreg[i4 * 4 + 2];
                acc += xv.w * Wreg[i4 * 4 + 3];
            }
            atomicAdd(&g_h1[d * HID_C + lane], acc * wj);
        }
    }
}

// Layer-2 messages: input = relu(h1). Half-warp per edge: c = lane&15 is the
// output channel; half = lane>>4 selects which of 2 concurrent edges.
// Each lane holds the full 32-dim W column for its channel (32 regs).
__global__ __launch_bounds__(512, 1)
void msg2_kernel(const float* __restrict__ W2, float* __restrict__ out) {
    const int r    = blockIdx.x;
    const int lane = threadIdx.x & 31;
    const int warp = threadIdx.x >> 5;
    const int c    = lane & 15;
    const int half = lane >> 4;

    float Wreg[HID_C];
    const float* Wr = W2 + r * HID_C * OUT_C;
#pragma unroll
    for (int k = 0; k < HID_C; k++) Wreg[k] = Wr[k * OUT_C + c];

    const int segStart = g_off[r];
    const int segEnd   = g_off[r + 1];
    const int wg = blockIdx.y * 16 + warp;
    const int nw = gridDim.y * 16;

    for (int base = segStart + wg * 32; base < segEnd; base += nw * 32) {
        int n = segEnd - base; if (n > 32) n = 32;
        int s32 = 0, d32 = 0; float w32 = 0.0f;
        if (lane < n) {
            s32 = gs_src[base + lane];
            d32 = gs_dst[base + lane];
            w32 = gs_w[base + lane];
        }
        int nPairs = (n + 1) >> 1;
#pragma unroll 2
        for (int jj = 0; jj < nPairs; jj++) {
            int ej = jj * 2 + half;
            bool act = ej < n;
            int sel = act ? ej : 0;
            int s = __shfl_sync(0xffffffffu, s32, sel);
            int d = __shfl_sync(0xffffffffu, d32, sel);
            float wj = __shfl_sync(0xffffffffu, w32, sel);
            const float4* hr = (const float4*)(g_h1 + s * HID_C);
            float acc = 0.0f;
#pragma unroll
            for (int k4 = 0; k4 < HID_C / 4; k4++) {
                float4 hv = hr[k4];
                acc += fmaxf(hv.x, 0.0f) * Wreg[k4 * 4 + 0];
                acc += fmaxf(hv.y, 0.0f) * Wreg[k4 * 4 + 1];
                acc += fmaxf(hv.z, 0.0f) * Wreg[k4 * 4 + 2];
                acc += fmaxf(hv.w, 0.0f) * Wreg[k4 * 4 + 3];
            }
            if (act) atomicAdd(&out[d * OUT_C + c], acc * wj);
        }
    }
}

// ---------------------------------------------------------------------------
extern "C" void kernel_launch(void* const* d_in, const int* in_sizes, int n_in,
                              void* d_out, int out_size) {
    const float* x          = (const float*)d_in[0];
    const int*   edge_index = (const int*)d_in[1];
    const int*   edge_type  = (const int*)d_in[2];
    const float* W1         = (const float*)d_in[3];
    const float* root1      = (const float*)d_in[4];
    const float* b1         = (const float*)d_in[5];
    const float* W2         = (const float*)d_in[6];
    const float* root2      = (const float*)d_in[7];
    const float* b2         = (const float*)d_in[8];
    float*       out        = (float*)d_out;

    (void)in_sizes; (void)n_in; (void)out_size;

    zero_kernel<<<2048, 256>>>();
    count_kernel<<<(N_EDGES + 255) / 256, 256>>>(edge_index, edge_type);
    scan_kernel<<<1, 32>>>();
    scatter_kernel<<<(N_EDGES + SCAT_EPB - 1) / SCAT_EPB, 256>>>(edge_index);

    root1_kernel<<<(N_NODES * HID_C + 255) / 256, 256>>>(x, root1, b1);
    msg1_kernel<<<dim3(N_REL, 6), 512>>>(x, W1);

    root2_kernel<<<(N_NODES * OUT_C + 255) / 256, 256>>>(root2, b2, out);
    msg2_kernel<<<dim3(N_REL, 6), 512>>>(W2, out);
}

// round 8
// speedup vs baseline: 1.5113x; 1.0081x over previous
#include <cuda_runtime.h>

#define N_NODES 50000
#define N_EDGES 1200000
#define N_REL   45
#define IN_C    64
#define HID_C   32
#define OUT_C   16

#define SCAT_EPB 2048   // edges per scatter block

// Scratch (device globals: no allocation allowed in kernel_launch)
__device__ int   g_cnt[N_REL * N_NODES];   // per-(rel,dst) edge counts
__device__ int   g_hist[N_REL];            // per-relation edge counts
__device__ int   g_off[N_REL + 1];         // exclusive scan of g_hist
__device__ int   g_cursor[N_REL];          // scatter cursors
__device__ unsigned g_done;                // count_kernel completion ticket
__device__ int   g_rel[N_EDGES];           // unsorted relation per edge
__device__ int   gs_src[N_EDGES];          // sorted-by-relation edge data
__device__ int   gs_dst[N_EDGES];
__device__ float gs_w[N_EDGES];
__device__ float g_h1[N_NODES * HID_C];    // layer-1 message sums (zero-init)
__device__ float g_hr[N_NODES * HID_C];    // relu(msg + x@root1 + b1)

// ---------------------------------------------------------------------------
__global__ void zero_kernel() {
    int i = blockIdx.x * blockDim.x + threadIdx.x;
    int stride = gridDim.x * blockDim.x;
    for (; i < N_REL * N_NODES; i += stride) g_cnt[i] = 0;
    int j = blockIdx.x * blockDim.x + threadIdx.x;
    for (; j < N_NODES * HID_C; j += stride) g_h1[j] = 0.0f;
    if (blockIdx.x == 0 && threadIdx.x < N_REL) g_hist[threadIdx.x] = 0;
    if (blockIdx.x == 0 && threadIdx.x == 0) g_done = 0;
}

// counts per (rel,dst) + per-relation histogram; LAST block does the 45-bin
// exclusive scan (ticket pattern) so no separate scan launch is needed.
__global__ void count_kernel(const int* __restrict__ edge_index,
                             const int* __restrict__ edge_type) {
    __shared__ int sh[N_REL];
    if (threadIdx.x < N_REL) sh[threadIdx.x] = 0;
    __syncthreads();
    int e = blockIdx.x * blockDim.x + threadIdx.x;
    if (e < N_EDGES) {
        int dst = edge_index[N_EDGES + e];
        int rel = edge_type[e];
        g_rel[e] = rel;
        atomicAdd(&g_cnt[rel * N_NODES + dst], 1);
        atomicAdd(&sh[rel], 1);
    }
    __syncthreads();
    if (threadIdx.x < N_REL) {
        atomicAdd(&g_hist[threadIdx.x], sh[threadIdx.x]);
        __threadfence();
    }
    __syncthreads();
    if (threadIdx.x == 0) {
        unsigned t = atomicInc(&g_done, 0xffffffffu);
        if (t == gridDim.x - 1) {          // last block: all g_hist adds visible
            int acc = 0;
            for (int r = 0; r < N_REL; r++) {
                g_off[r] = acc;
                g_cursor[r] = acc;
                acc += g_hist[r];
            }
            g_off[N_REL] = acc;
        }
    }
}

// Hierarchical-cursor relation sort; folds mean weight 1/cnt.
__global__ __launch_bounds__(256)
void scatter_kernel(const int* __restrict__ edge_index) {
    __shared__ int sh_cnt[N_REL];
    __shared__ int sh_base[N_REL];
    const int blockStart = blockIdx.x * SCAT_EPB;

    if (threadIdx.x < N_REL) sh_cnt[threadIdx.x] = 0;
    __syncthreads();

    for (int i = threadIdx.x; i < SCAT_EPB; i += blockDim.x) {
        int e = blockStart + i;
        if (e < N_EDGES) atomicAdd(&sh_cnt[g_rel[e]], 1);
    }
    __syncthreads();

    if (threadIdx.x < N_REL) {
        sh_base[threadIdx.x] = atomicAdd(&g_cursor[threadIdx.x], sh_cnt[threadIdx.x]);
        sh_cnt[threadIdx.x] = 0;
    }
    __syncthreads();

    for (int i = threadIdx.x; i < SCAT_EPB; i += blockDim.x) {
        int e = blockStart + i;
        if (e >= N_EDGES) continue;
        int rel = g_rel[e];
        int pos = sh_base[rel] + atomicAdd(&sh_cnt[rel], 1);
        int src = edge_index[e];
        int dst = edge_index[N_EDGES + e];
        int c   = g_cnt[rel * N_NODES + dst];
        gs_src[pos] = src;
        gs_dst[pos] = dst;
        gs_w[pos]   = 1.0f / (float)(c > 0 ? c : 1);
    }
}

// ---------------------------------------------------------------------------
// Layer-1 messages over relation-sorted edges into zero-initialized g_h1.
// blockIdx.x = relation; W column register-resident (lane = channel).
// grid (45, 6) x 512 threads = 270 blocks = one wave. 4 accumulator chains.
__global__ __launch_bounds__(512, 1)
void msg1_kernel(const float* __restrict__ x, const float* __restrict__ W1) {
    const int r    = blockIdx.x;
    const int lane = threadIdx.x & 31;
    const int warp = threadIdx.x >> 5;   // 0..15

    float Wreg[IN_C];
    const float* Wr = W1 + r * IN_C * HID_C;
#pragma unroll
    for (int i = 0; i < IN_C; i++) Wreg[i] = Wr[i * HID_C + lane];

    const int segStart = g_off[r];
    const int segEnd   = g_off[r + 1];
    const int wg = blockIdx.y * 16 + warp;
    const int nw = gridDim.y * 16;

    for (int base = segStart + wg * 32; base < segEnd; base += nw * 32) {
        int n = segEnd - base; if (n > 32) n = 32;
        int s32 = 0, d32 = 0; float w32 = 0.0f;
        if (lane < n) {
            s32 = gs_src[base + lane];
            d32 = gs_dst[base + lane];
            w32 = gs_w[base + lane];
        }
#pragma unroll 4
        for (int j = 0; j < n; j++) {
            int s = __shfl_sync(0xffffffffu, s32, j);
            int d = __shfl_sync(0xffffffffu, d32, j);
            float wj = __shfl_sync(0xffffffffu, w32, j);
            const float4* xr = (const float4*)(x + s * IN_C);
            float a0 = 0.0f, a1 = 0.0f, a2 = 0.0f, a3 = 0.0f;
#pragma unroll
            for (int q = 0; q < IN_C / 16; q++) {      // 4 groups of 4 float4
                float4 v0 = xr[q * 4 + 0];
                float4 v1 = xr[q * 4 + 1];
                float4 v2 = xr[q * 4 + 2];
                float4 v3 = xr[q * 4 + 3];
                a0 += v0.x * Wreg[q * 16 + 0];  a0 += v0.y * Wreg[q * 16 + 1];
                a0 += v0.z * Wreg[q * 16 + 2];  a0 += v0.w * Wreg[q * 16 + 3];
                a1 += v1.x * Wreg[q * 16 + 4];  a1 += v1.y * Wreg[q * 16 + 5];
                a1 += v1.z * Wreg[q * 16 + 6];  a1 += v1.w * Wreg[q * 16 + 7];
                a2 += v2.x * Wreg[q * 16 + 8];  a2 += v2.y * Wreg[q * 16 + 9];
                a2 += v2.z * Wreg[q * 16 + 10]; a2 += v2.w * Wreg[q * 16 + 11];
                a3 += v3.x * Wreg[q * 16 + 12]; a3 += v3.y * Wreg[q * 16 + 13];
                a3 += v3.z * Wreg[q * 16 + 14]; a3 += v3.w * Wreg[q * 16 + 15];
            }
            float acc = (a0 + a1) + (a2 + a3);
            atomicAdd(&g_h1[d * HID_C + lane], acc * wj);
        }
    }
}

// g_hr[n,c] = relu(g_h1[n,c] + b1[c] + sum_i x[n,i]*root1[i,c])
__global__ void root1_relu_kernel(const float* __restrict__ x,
                                  const float* __restrict__ root,
                                  const float* __restrict__ b) {
    int t = blockIdx.x * blockDim.x + threadIdx.x;
    if (t >= N_NODES * HID_C) return;
    int n = t >> 5;
    int c = t & 31;
    float acc = b[c] + g_h1[t];
    const float4* xr = (const float4*)(x + n * IN_C);
#pragma unroll
    for (int i4 = 0; i4 < IN_C / 4; i4++) {
        float4 xv = xr[i4];
        acc += xv.x * root[(i4 * 4 + 0) * HID_C + c];
        acc += xv.y * root[(i4 * 4 + 1) * HID_C + c];
        acc += xv.z * root[(i4 * 4 + 2) * HID_C + c];
        acc += xv.w * root[(i4 * 4 + 3) * HID_C + c];
    }
    g_hr[t] = fmaxf(acc, 0.0f);
}

// out[n, c] = b2[c] + sum_i g_hr[n, i] * root2[i, c]
__global__ void root2_kernel(const float* __restrict__ root,
                             const float* __restrict__ b,
                             float* __restrict__ out) {
    int t = blockIdx.x * blockDim.x + threadIdx.x;
    if (t >= N_NODES * OUT_C) return;
    int n = t >> 4;
    int c = t & 15;
    float acc = b[c];
    const float4* hr = (const float4*)(g_hr + n * HID_C);
#pragma unroll
    for (int i4 = 0; i4 < HID_C / 4; i4++) {
        float4 hv = hr[i4];
        acc += hv.x * root[(i4 * 4 + 0) * OUT_C + c];
        acc += hv.y * root[(i4 * 4 + 1) * OUT_C + c];
        acc += hv.z * root[(i4 * 4 + 2) * OUT_C + c];
        acc += hv.w * root[(i4 * 4 + 3) * OUT_C + c];
    }
    out[t] = acc;
}

// Layer-2 messages over g_hr (already ReLU'd). Half-warp per edge:
// c = lane&15 output channel; half = lane>>4 picks one of 2 edges.
__global__ __launch_bounds__(512, 1)
void msg2_kernel(const float* __restrict__ W2, float* __restrict__ out) {
    const int r    = blockIdx.x;
    const int lane = threadIdx.x & 31;
    const int warp = threadIdx.x >> 5;
    const int c    = lane & 15;
    const int half = lane >> 4;

    float Wreg[HID_C];
    const float* Wr = W2 + r * HID_C * OUT_C;
#pragma unroll
    for (int k = 0; k < HID_C; k++) Wreg[k] = Wr[k * OUT_C + c];

    const int segStart = g_off[r];
    const int segEnd   = g_off[r + 1];
    const int wg = blockIdx.y * 16 + warp;
    const int nw = gridDim.y * 16;

    for (int base = segStart + wg * 32; base < segEnd; base += nw * 32) {
        int n = segEnd - base; if (n > 32) n = 32;
        int s32 = 0, d32 = 0; float w32 = 0.0f;
        if (lane < n) {
            s32 = gs_src[base + lane];
            d32 = gs_dst[base + lane];
            w32 = gs_w[base + lane];
        }
        int nPairs = (n + 1) >> 1;
#pragma unroll 2
        for (int jj = 0; jj < nPairs; jj++) {
            int ej = jj * 2 + half;
            bool act = ej < n;
            int sel = act ? ej : 0;
            int s = __shfl_sync(0xffffffffu, s32, sel);
            int d = __shfl_sync(0xffffffffu, d32, sel);
            float wj = __shfl_sync(0xffffffffu, w32, sel);
            const float4* hr = (const float4*)(g_hr + s * HID_C);
            float a0 = 0.0f, a1 = 0.0f;
#pragma unroll
            for (int k4 = 0; k4 < HID_C / 8; k4++) {
                float4 h0 = hr[k4 * 2 + 0];
                float4 h1 = hr[k4 * 2 + 1];
                a0 += h0.x * Wreg[k4 * 8 + 0]; a0 += h0.y * Wreg[k4 * 8 + 1];
                a0 += h0.z * Wreg[k4 * 8 + 2]; a0 += h0.w * Wreg[k4 * 8 + 3];
                a1 += h1.x * Wreg[k4 * 8 + 4]; a1 += h1.y * Wreg[k4 * 8 + 5];
                a1 += h1.z * Wreg[k4 * 8 + 6]; a1 += h1.w * Wreg[k4 * 8 + 7];
            }
            if (act) atomicAdd(&out[d * OUT_C + c], (a0 + a1) * wj);
        }
    }
}

// ---------------------------------------------------------------------------
extern "C" void kernel_launch(void* const* d_in, const int* in_sizes, int n_in,
                              void* d_out, int out_size) {
    const float* x          = (const float*)d_in[0];
    const int*   edge_index = (const int*)d_in[1];
    const int*   edge_type  = (const int*)d_in[2];
    const float* W1         = (const float*)d_in[3];
    const float* root1      = (const float*)d_in[4];
    const float* b1         = (const float*)d_in[5];
    const float* W2         = (const float*)d_in[6];
    const float* root2      = (const float*)d_in[7];
    const float* b2         = (const float*)d_in[8];
    float*       out        = (float*)d_out;

    (void)in_sizes; (void)n_in; (void)out_size;

    zero_kernel<<<2048, 256>>>();                                   // 1
    count_kernel<<<(N_EDGES + 255) / 256, 256>>>(edge_index, edge_type); // 2 (+scan)
    scatter_kernel<<<(N_EDGES + SCAT_EPB - 1) / SCAT_EPB, 256>>>(edge_index); // 3
    msg1_kernel<<<dim3(N_REL, 6), 512>>>(x, W1);                    // 4 <- profiled
    root1_relu_kernel<<<(N_NODES * HID_C + 255) / 256, 256>>>(x, root1, b1); // 5
    root2_kernel<<<(N_NODES * OUT_C + 255) / 256, 256>>>(root2, b2, out);    // 6
    msg2_kernel<<<dim3(N_REL, 6), 512>>>(W2, out);                  // 7
}

// round 9
// speedup vs baseline: 1.9700x; 1.3035x over previous
#include <cuda_runtime.h>

#define N_NODES 50000
#define N_EDGES 1200000
#define N_REL   45
#define IN_C    64
#define HID_C   32
#define OUT_C   16

#define SCAT_EPB 2048   // edges per scatter block
#define ROW_PAD  80     // smem row stride in floats (320B: conflict-free phases)

// Scratch (device globals: no allocation allowed in kernel_launch)
__device__ int   g_cnt[N_REL * N_NODES];   // per-(rel,dst) edge counts
__device__ int   g_hist[N_REL];            // per-relation edge counts
__device__ int   g_off[N_REL + 1];         // exclusive scan of g_hist
__device__ int   g_cursor[N_REL];          // scatter cursors
__device__ unsigned g_done;                // count_kernel completion ticket
__device__ int   g_rel[N_EDGES];           // unsorted relation per edge
__device__ int   gs_src[N_EDGES];          // sorted-by-relation edge data
__device__ int   gs_dst[N_EDGES];
__device__ float gs_w[N_EDGES];
__device__ float g_h1[N_NODES * HID_C];    // layer-1 message sums (zero-init)
__device__ float g_hr[N_NODES * HID_C];    // relu(msg + x@root1 + b1)

// ---------------------------------------------------------------------------
__global__ void zero_kernel() {
    int i = blockIdx.x * blockDim.x + threadIdx.x;
    int stride = gridDim.x * blockDim.x;
    for (; i < N_REL * N_NODES; i += stride) g_cnt[i] = 0;
    int j = blockIdx.x * blockDim.x + threadIdx.x;
    for (; j < N_NODES * HID_C; j += stride) g_h1[j] = 0.0f;
    if (blockIdx.x == 0 && threadIdx.x < N_REL) g_hist[threadIdx.x] = 0;
    if (blockIdx.x == 0 && threadIdx.x == 0) g_done = 0;
}

// counts per (rel,dst) + per-relation histogram; LAST block does the 45-bin
// exclusive scan (ticket pattern) so no separate scan launch is needed.
__global__ void count_kernel(const int* __restrict__ edge_index,
                             const int* __restrict__ edge_type) {
    __shared__ int sh[N_REL];
    if (threadIdx.x < N_REL) sh[threadIdx.x] = 0;
    __syncthreads();
    int e = blockIdx.x * blockDim.x + threadIdx.x;
    if (e < N_EDGES) {
        int dst = edge_index[N_EDGES + e];
        int rel = edge_type[e];
        g_rel[e] = rel;
        atomicAdd(&g_cnt[rel * N_NODES + dst], 1);
        atomicAdd(&sh[rel], 1);
    }
    __syncthreads();
    if (threadIdx.x < N_REL) {
        atomicAdd(&g_hist[threadIdx.x], sh[threadIdx.x]);
        __threadfence();
    }
    __syncthreads();
    if (threadIdx.x == 0) {
        unsigned t = atomicInc(&g_done, 0xffffffffu);
        if (t == gridDim.x - 1) {          // last block: all g_hist adds visible
            int acc = 0;
            for (int r = 0; r < N_REL; r++) {
                g_off[r] = acc;
                g_cursor[r] = acc;
                acc += g_hist[r];
            }
            g_off[N_REL] = acc;
        }
    }
}

// Hierarchical-cursor relation sort; folds mean weight 1/cnt.
__global__ __launch_bounds__(256)
void scatter_kernel(const int* __restrict__ edge_index) {
    __shared__ int sh_cnt[N_REL];
    __shared__ int sh_base[N_REL];
    const int blockStart = blockIdx.x * SCAT_EPB;

    if (threadIdx.x < N_REL) sh_cnt[threadIdx.x] = 0;
    __syncthreads();

    for (int i = threadIdx.x; i < SCAT_EPB; i += blockDim.x) {
        int e = blockStart + i;
        if (e < N_EDGES) atomicAdd(&sh_cnt[g_rel[e]], 1);
    }
    __syncthreads();

    if (threadIdx.x < N_REL) {
        sh_base[threadIdx.x] = atomicAdd(&g_cursor[threadIdx.x], sh_cnt[threadIdx.x]);
        sh_cnt[threadIdx.x] = 0;
    }
    __syncthreads();

    for (int i = threadIdx.x; i < SCAT_EPB; i += blockDim.x) {
        int e = blockStart + i;
        if (e >= N_EDGES) continue;
        int rel = g_rel[e];
        int pos = sh_base[rel] + atomicAdd(&sh_cnt[rel], 1);
        int src = edge_index[e];
        int dst = edge_index[N_EDGES + e];
        int c   = g_cnt[rel * N_NODES + dst];
        gs_src[pos] = src;
        gs_dst[pos] = dst;
        gs_w[pos]   = 1.0f / (float)(c > 0 ? c : 1);
    }
}

// ---------------------------------------------------------------------------
// Layer-1 messages over relation-sorted edges into zero-initialized g_h1.
// blockIdx.x = relation; W column register-resident (lane = channel).
// Gather path: 8 x-rows loaded COALESCED (4 lanes/row, float4) into a
// warp-private smem tile, then broadcast LDS.128 reads. This replaces 16
// broadcast LDG.128/edge (the 79%-L1 bottleneck) with ~2 coalesced LDG +
// 2 STS + 16 one-cycle LDS per edge.
__global__ __launch_bounds__(512, 1)
void msg1_kernel(const float* __restrict__ x, const float* __restrict__ W1) {
    __shared__ float stage[16][8 * ROW_PAD];   // 16 warps x 8 rows -> 40KB
    const int r    = blockIdx.x;
    const int lane = threadIdx.x & 31;
    const int warp = threadIdx.x >> 5;   // 0..15
    float* st = stage[warp];

    float Wreg[IN_C];
    const float* Wr = W1 + r * IN_C * HID_C;
#pragma unroll
    for (int i = 0; i < IN_C; i++) Wreg[i] = Wr[i * HID_C + lane];

    const int segStart = g_off[r];
    const int segEnd   = g_off[r + 1];
    const int wg = blockIdx.y * 16 + warp;
    const int nw = gridDim.y * 16;

    const int row  = lane >> 2;   // 0..7 : which staged row this lane loads
    const int part = lane & 3;    // 0..3 : which 64B quarter of the row

    for (int base = segStart + wg * 32; base < segEnd; base += nw * 32) {
        int n = segEnd - base; if (n > 32) n = 32;
        int s32 = 0, d32 = 0; float w32 = 0.0f;
        if (lane < n) {
            s32 = gs_src[base + lane];
            d32 = gs_dst[base + lane];
            w32 = gs_w[base + lane];
        }
#pragma unroll
        for (int g = 0; g < 4; g++) {
            int m = n - g * 8; if (m <= 0) break; if (m > 8) m = 8;
            // coalesced gather of up to 8 rows into smem
            int s = __shfl_sync(0xffffffffu, s32, g * 8 + (row < m ? row : 0));
            if (row < m) {
                const float4* src4 = (const float4*)(x + s * IN_C);
#pragma unroll
                for (int k = 0; k < 4; k++) {
                    float4 v = src4[part + 4 * k];
                    *(float4*)&st[row * ROW_PAD + (part + 4 * k) * 4] = v;
                }
            }
            __syncwarp();
            for (int j = 0; j < m; j++) {
                int d = __shfl_sync(0xffffffffu, d32, g * 8 + j);
                float wj = __shfl_sync(0xffffffffu, w32, g * 8 + j);
                const float4* xr = (const float4*)&st[j * ROW_PAD];
                float a0 = 0.0f, a1 = 0.0f, a2 = 0.0f, a3 = 0.0f;
#pragma unroll
                for (int q = 0; q < IN_C / 16; q++) {
                    float4 v0 = xr[q * 4 + 0];
                    float4 v1 = xr[q * 4 + 1];
                    float4 v2 = xr[q * 4 + 2];
                    float4 v3 = xr[q * 4 + 3];
                    a0 += v0.x * Wreg[q * 16 + 0];  a0 += v0.y * Wreg[q * 16 + 1];
                    a0 += v0.z * Wreg[q * 16 + 2];  a0 += v0.w * Wreg[q * 16 + 3];
                    a1 += v1.x * Wreg[q * 16 + 4];  a1 += v1.y * Wreg[q * 16 + 5];
                    a1 += v1.z * Wreg[q * 16 + 6];  a1 += v1.w * Wreg[q * 16 + 7];
                    a2 += v2.x * Wreg[q * 16 + 8];  a2 += v2.y * Wreg[q * 16 + 9];
                    a2 += v2.z * Wreg[q * 16 + 10]; a2 += v2.w * Wreg[q * 16 + 11];
                    a3 += v3.x * Wreg[q * 16 + 12]; a3 += v3.y * Wreg[q * 16 + 13];
                    a3 += v3.z * Wreg[q * 16 + 14]; a3 += v3.w * Wreg[q * 16 + 15];
                }
                float acc = (a0 + a1) + (a2 + a3);
                atomicAdd(&g_h1[d * HID_C + lane], acc * wj);
            }
            __syncwarp();
        }
    }
}

// g_hr[n,c] = relu(g_h1[n,c] + b1[c] + sum_i x[n,i]*root1[i,c])
__global__ void root1_relu_kernel(const float* __restrict__ x,
                                  const float* __restrict__ root,
                                  const float* __restrict__ b) {
    int t = blockIdx.x * blockDim.x + threadIdx.x;
    if (t >= N_NODES * HID_C) return;
    int n = t >> 5;
    int c = t & 31;
    float acc = b[c] + g_h1[t];
    const float4* xr = (const float4*)(x + n * IN_C);
#pragma unroll
    for (int i4 = 0; i4 < IN_C / 4; i4++) {
        float4 xv = xr[i4];
        acc += xv.x * root[(i4 * 4 + 0) * HID_C + c];
        acc += xv.y * root[(i4 * 4 + 1) * HID_C + c];
        acc += xv.z * root[(i4 * 4 + 2) * HID_C + c];
        acc += xv.w * root[(i4 * 4 + 3) * HID_C + c];
    }
    g_hr[t] = fmaxf(acc, 0.0f);
}

// out[n, c] = b2[c] + sum_i g_hr[n, i] * root2[i, c]
__global__ void root2_kernel(const float* __restrict__ root,
                             const float* __restrict__ b,
                             float* __restrict__ out) {
    int t = blockIdx.x * blockDim.x + threadIdx.x;
    if (t >= N_NODES * OUT_C) return;
    int n = t >> 4;
    int c = t & 15;
    float acc = b[c];
    const float4* hr = (const float4*)(g_hr + n * HID_C);
#pragma unroll
    for (int i4 = 0; i4 < HID_C / 4; i4++) {
        float4 hv = hr[i4];
        acc += hv.x * root[(i4 * 4 + 0) * OUT_C + c];
        acc += hv.y * root[(i4 * 4 + 1) * OUT_C + c];
        acc += hv.z * root[(i4 * 4 + 2) * OUT_C + c];
        acc += hv.w * root[(i4 * 4 + 3) * OUT_C + c];
    }
    out[t] = acc;
}

// Layer-2 messages over g_hr (already ReLU'd). Half-warp per edge:
// c = lane&15 output channel; half = lane>>4 picks one of 2 edges.
__global__ __launch_bounds__(512, 1)
void msg2_kernel(const float* __restrict__ W2, float* __restrict__ out) {
    const int r    = blockIdx.x;
    const int lane = threadIdx.x & 31;
    const int warp = threadIdx.x >> 5;
    const int c    = lane & 15;
    const int half = lane >> 4;

    float Wreg[HID_C];
    const float* Wr = W2 + r * HID_C * OUT_C;
#pragma unroll
    for (int k = 0; k < HID_C; k++) Wreg[k] = Wr[k * OUT_C + c];

    const int segStart = g_off[r];
    const int segEnd   = g_off[r + 1];
    const int wg = blockIdx.y * 16 + warp;
    const int nw = gridDim.y * 16;

    for (int base = segStart + wg * 32; base < segEnd; base += nw * 32) {
        int n = segEnd - base; if (n > 32) n = 32;
        int s32 = 0, d32 = 0; float w32 = 0.0f;
        if (lane < n) {
            s32 = gs_src[base + lane];
            d32 = gs_dst[base + lane];
            w32 = gs_w[base + lane];
        }
        int nPairs = (n + 1) >> 1;
#pragma unroll 2
        for (int jj = 0; jj < nPairs; jj++) {
            int ej = jj * 2 + half;
            bool act = ej < n;
            int sel = act ? ej : 0;
            int s = __shfl_sync(0xffffffffu, s32, sel);
            int d = __shfl_sync(0xffffffffu, d32, sel);
            float wj = __shfl_sync(0xffffffffu, w32, sel);
            const float4* hr = (const float4*)(g_hr + s * HID_C);
            float a0 = 0.0f, a1 = 0.0f;
#pragma unroll
            for (int k4 = 0; k4 < HID_C / 8; k4++) {
                float4 h0 = hr[k4 * 2 + 0];
                float4 h1 = hr[k4 * 2 + 1];
                a0 += h0.x * Wreg[k4 * 8 + 0]; a0 += h0.y * Wreg[k4 * 8 + 1];
                a0 += h0.z * Wreg[k4 * 8 + 2]; a0 += h0.w * Wreg[k4 * 8 + 3];
                a1 += h1.x * Wreg[k4 * 8 + 4]; a1 += h1.y * Wreg[k4 * 8 + 5];
                a1 += h1.z * Wreg[k4 * 8 + 6]; a1 += h1.w * Wreg[k4 * 8 + 7];
            }
            if (act) atomicAdd(&out[d * OUT_C + c], (a0 + a1) * wj);
        }
    }
}

// ---------------------------------------------------------------------------
extern "C" void kernel_launch(void* const* d_in, const int* in_sizes, int n_in,
                              void* d_out, int out_size) {
    const float* x          = (const float*)d_in[0];
    const int*   edge_index = (const int*)d_in[1];
    const int*   edge_type  = (const int*)d_in[2];
    const float* W1         = (const float*)d_in[3];
    const float* root1      = (const float*)d_in[4];
    const float* b1         = (const float*)d_in[5];
    const float* W2         = (const float*)d_in[6];
    const float* root2      = (const float*)d_in[7];
    const float* b2         = (const float*)d_in[8];
    float*       out        = (float*)d_out;

    (void)in_sizes; (void)n_in; (void)out_size;

    zero_kernel<<<2048, 256>>>();                                   // 1
    count_kernel<<<(N_EDGES + 255) / 256, 256>>>(edge_index, edge_type); // 2 (+scan)
    scatter_kernel<<<(N_EDGES + SCAT_EPB - 1) / SCAT_EPB, 256>>>(edge_index); // 3
    msg1_kernel<<<dim3(N_REL, 6), 512>>>(x, W1);                    // 4 <- profiled
    root1_relu_kernel<<<(N_NODES * HID_C + 255) / 256, 256>>>(x, root1, b1); // 5
    root2_kernel<<<(N_NODES * OUT_C + 255) / 256, 256>>>(root2, b2, out);    // 6
    msg2_kernel<<<dim3(N_REL, 6), 512>>>(W2, out);                  // 7
}

// round 11
// speedup vs baseline: 2.0037x; 1.0171x over previous
#include <cuda_runtime.h>

#define N_NODES 50000
#define N_EDGES 1200000
#define N_REL   45
#define IN_C    64
#define HID_C   32
#define OUT_C   16

#define SCAT_EPB 2048   // edges per scatter block
#define ROW_PAD  80     // smem row stride in floats (320B)

// Scratch (device globals: no allocation allowed in kernel_launch)
__device__ int   g_cnt[N_REL * N_NODES];   // per-(rel,dst) edge counts
__device__ int   g_hist[N_REL];            // per-relation edge counts
__device__ int   g_off[N_REL + 1];         // exclusive scan of g_hist
__device__ int   g_cursor[N_REL];          // scatter cursors
__device__ unsigned g_done;                // count_kernel completion ticket
__device__ int   g_rel[N_EDGES];           // unsorted relation per edge
__device__ int   gs_src[N_EDGES];          // sorted-by-relation edge data
__device__ int   gs_dst[N_EDGES];
__device__ float gs_w[N_EDGES];
__device__ float g_h1[N_NODES * HID_C];    // layer-1 message sums (zero-init)
__device__ float g_hr[N_NODES * HID_C];    // relu(msg + x@root1 + b1)

// ---------------------------------------------------------------------------
__global__ void zero_kernel() {
    int i = blockIdx.x * blockDim.x + threadIdx.x;
    int stride = gridDim.x * blockDim.x;
    for (; i < N_REL * N_NODES; i += stride) g_cnt[i] = 0;
    int j = blockIdx.x * blockDim.x + threadIdx.x;
    for (; j < N_NODES * HID_C; j += stride) g_h1[j] = 0.0f;
    if (blockIdx.x == 0 && threadIdx.x < N_REL) g_hist[threadIdx.x] = 0;
    if (blockIdx.x == 0 && threadIdx.x == 0) g_done = 0;
}

// counts per (rel,dst) + per-relation histogram; LAST block does the 45-bin
// exclusive scan (ticket pattern) so no separate scan launch is needed.
__global__ void count_kernel(const int* __restrict__ edge_index,
                             const int* __restrict__ edge_type) {
    __shared__ int sh[N_REL];
    if (threadIdx.x < N_REL) sh[threadIdx.x] = 0;
    __syncthreads();
    int e = blockIdx.x * blockDim.x + threadIdx.x;
    if (e < N_EDGES) {
        int dst = edge_index[N_EDGES + e];
        int rel = edge_type[e];
        g_rel[e] = rel;
        atomicAdd(&g_cnt[rel * N_NODES + dst], 1);
        atomicAdd(&sh[rel], 1);
    }
    __syncthreads();
    if (threadIdx.x < N_REL) {
        atomicAdd(&g_hist[threadIdx.x], sh[threadIdx.x]);
        __threadfence();
    }
    __syncthreads();
    if (threadIdx.x == 0) {
        unsigned t = atomicInc(&g_done, 0xffffffffu);
        if (t == gridDim.x - 1) {
            int acc = 0;
            for (int r = 0; r < N_REL; r++) {
                g_off[r] = acc;
                g_cursor[r] = acc;
                acc += g_hist[r];
            }
            g_off[N_REL] = acc;
        }
    }
}

// Hierarchical-cursor relation sort; folds mean weight 1/cnt.
__global__ __launch_bounds__(256)
void scatter_kernel(const int* __restrict__ edge_index) {
    __shared__ int sh_cnt[N_REL];
    __shared__ int sh_base[N_REL];
    const int blockStart = blockIdx.x * SCAT_EPB;

    if (threadIdx.x < N_REL) sh_cnt[threadIdx.x] = 0;
    __syncthreads();
    for (int i = threadIdx.x; i < SCAT_EPB; i += blockDim.x) {
        int e = blockStart + i;
        if (e < N_EDGES) atomicAdd(&sh_cnt[g_rel[e]], 1);
    }
    __syncthreads();
    if (threadIdx.x < N_REL) {
        sh_base[threadIdx.x] = atomicAdd(&g_cursor[threadIdx.x], sh_cnt[threadIdx.x]);
        sh_cnt[threadIdx.x] = 0;
    }
    __syncthreads();
    for (int i = threadIdx.x; i < SCAT_EPB; i += blockDim.x) {
        int e = blockStart + i;
        if (e >= N_EDGES) continue;
        int rel = g_rel[e];
        int pos = sh_base[rel] + atomicAdd(&sh_cnt[rel], 1);
        int src = edge_index[e];
        int dst = edge_index[N_EDGES + e];
        int c   = g_cnt[rel * N_NODES + dst];
        gs_src[pos] = src;
        gs_dst[pos] = dst;
        gs_w[pos]   = 1.0f / (float)(c > 0 ? c : 1);
    }
}

// ---------------------------------------------------------------------------
// Layer-1 messages over relation-sorted edges into zero-initialized g_h1.
// blockIdx.x = relation; W column register-resident (lane = channel).
// 256-thread blocks, 2 blocks/SM (grid 270 <= 296 slots -> single wave).
// Double-buffered 8-row smem staging: group g+1's coalesced LDGs are issued
// before computing group g, hiding gather latency behind FFMA.
__global__ __launch_bounds__(256, 2)
void msg1_kernel(const float* __restrict__ x, const float* __restrict__ W1) {
    __shared__ float stage[8][2][8 * ROW_PAD];   // 8 warps x 2 bufs -> 40KB
    const int r    = blockIdx.x;
    const int lane = threadIdx.x & 31;
    const int warp = threadIdx.x >> 5;   // 0..7

    float Wreg[IN_C];
    const float* Wr = W1 + r * IN_C * HID_C;
#pragma unroll
    for (int i = 0; i < IN_C; i++) Wreg[i] = Wr[i * HID_C + lane];

    const int segStart = g_off[r];
    const int segEnd   = g_off[r + 1];
    const int wg = blockIdx.y * 8 + warp;
    const int nw = gridDim.y * 8;

    const int row  = lane >> 2;   // 0..7 : staged row this lane gathers
    const int part = lane & 3;    // 0..3 : 64B quarter of the row

    for (int base = segStart + wg * 32; base < segEnd; base += nw * 32) {
        int n = segEnd - base; if (n > 32) n = 32;
        int s32 = 0, d32 = 0; float w32 = 0.0f;
        if (lane < n) {
            s32 = gs_src[base + lane];
            d32 = gs_dst[base + lane];
            w32 = gs_w[base + lane];
        }
        int ngroups = (n + 7) >> 3;

        // prologue: gather group 0 -> buf 0
        {
            int m0 = n < 8 ? n : 8;
            int s = __shfl_sync(0xffffffffu, s32, (row < m0 ? row : 0));
            if (row < m0) {
                const float4* src4 = (const float4*)(x + (size_t)s * IN_C);
                float* dstp = &stage[warp][0][row * ROW_PAD];
#pragma unroll
                for (int k = 0; k < 4; k++)
                    *(float4*)&dstp[(part + 4 * k) * 4] = src4[part + 4 * k];
            }
        }
        __syncwarp();

        for (int g = 0; g < ngroups; g++) {
            int m = n - g * 8; if (m > 8) m = 8;

            // prefetch group g+1's rows into registers (LDG overlaps compute)
            float4 rv0, rv1, rv2, rv3;
            bool pf = false;
            if (g + 1 < ngroups) {
                int m1 = n - (g + 1) * 8; if (m1 > 8) m1 = 8;
                int s = __shfl_sync(0xffffffffu, s32,
                                    (g + 1) * 8 + (row < m1 ? row : 0));
                if (row < m1) {
                    const float4* src4 = (const float4*)(x + (size_t)s * IN_C);
                    rv0 = src4[part + 0];
                    rv1 = src4[part + 4];
                    rv2 = src4[part + 8];
                    rv3 = src4[part + 12];
                    pf = true;
                }
            }

            // compute group g from buf (g&1)
            const float* buf = stage[warp][g & 1];
            for (int j = 0; j < m; j++) {
                int d = __shfl_sync(0xffffffffu, d32, g * 8 + j);
                float wj = __shfl_sync(0xffffffffu, w32, g * 8 + j);
                const float4* xr = (const float4*)&buf[j * ROW_PAD];
                float a0 = 0.0f, a1 = 0.0f, a2 = 0.0f, a3 = 0.0f;
#pragma unroll
                for (int q = 0; q < IN_C / 16; q++) {
                    float4 v0 = xr[q * 4 + 0];
                    float4 v1 = xr[q * 4 + 1];
                    float4 v2 = xr[q * 4 + 2];
                    float4 v3 = xr[q * 4 + 3];
                    a0 += v0.x * Wreg[q * 16 + 0];  a0 += v0.y * Wreg[q * 16 + 1];
                    a0 += v0.z * Wreg[q * 16 + 2];  a0 += v0.w * Wreg[q * 16 + 3];
                    a1 += v1.x * Wreg[q * 16 + 4];  a1 += v1.y * Wreg[q * 16 + 5];
                    a1 += v1.z * Wreg[q * 16 + 6];  a1 += v1.w * Wreg[q * 16 + 7];
                    a2 += v2.x * Wreg[q * 16 + 8];  a2 += v2.y * Wreg[q * 16 + 9];
                    a2 += v2.z * Wreg[q * 16 + 10]; a2 += v2.w * Wreg[q * 16 + 11];
                    a3 += v3.x * Wreg[q * 16 + 12]; a3 += v3.y * Wreg[q * 16 + 13];
                    a3 += v3.z * Wreg[q * 16 + 14]; a3 += v3.w * Wreg[q * 16 + 15];
                }
                float acc = (a0 + a1) + (a2 + a3);
                atomicAdd(&g_h1[d * HID_C + lane], acc * wj);
            }

            // store prefetched rows into the other buffer
            if (pf) {
                float* dstp = &stage[warp][(g + 1) & 1][row * ROW_PAD];
                *(float4*)&dstp[(part + 0) * 4]  = rv0;
                *(float4*)&dstp[(part + 4) * 4]  = rv1;
                *(float4*)&dstp[(part + 8) * 4]  = rv2;
                *(float4*)&dstp[(part + 12) * 4] = rv3;
            }
            __syncwarp();
        }
    }
}

// ---------------------------------------------------------------------------
// g_hr[n,c] = relu(g_h1[n,c] + b1[c] + sum_i x[n,i]*root1[i,c])
__global__ void root1_relu_kernel(const float* __restrict__ x,
                                  const float* __restrict__ root,
                                  const float* __restrict__ b) {
    int t = blockIdx.x * blockDim.x + threadIdx.x;
    if (t >= N_NODES * HID_C) return;
    int n = t >> 5;
    int c = t & 31;
    float acc = b[c] + g_h1[t];
    const float4* xr = (const float4*)(x + n * IN_C);
#pragma unroll
    for (int i4 = 0; i4 < IN_C / 4; i4++) {
        float4 xv = xr[i4];
        acc += xv.x * root[(i4 * 4 + 0) * HID_C + c];
        acc += xv.y * root[(i4 * 4 + 1) * HID_C + c];
        acc += xv.z * root[(i4 * 4 + 2) * HID_C + c];
        acc += xv.w * root[(i4 * 4 + 3) * HID_C + c];
    }
    g_hr[t] = fmaxf(acc, 0.0f);
}

// out[n, c] = b2[c] + sum_i g_hr[n, i] * root2[i, c]
__global__ void root2_kernel(const float* __restrict__ root,
                             const float* __restrict__ b,
                             float* __restrict__ out) {
    int t = blockIdx.x * blockDim.x + threadIdx.x;
    if (t >= N_NODES * OUT_C) return;
    int n = t >> 4;
    int c = t & 15;
    float acc = b[c];
    const float4* hr = (const float4*)(g_hr + n * HID_C);
#pragma unroll
    for (int i4 = 0; i4 < HID_C / 4; i4++) {
        float4 hv = hr[i4];
        acc += hv.x * root[(i4 * 4 + 0) * OUT_C + c];
        acc += hv.y * root[(i4 * 4 + 1) * OUT_C + c];
        acc += hv.z * root[(i4 * 4 + 2) * OUT_C + c];
        acc += hv.w * root[(i4 * 4 + 3) * OUT_C + c];
    }
    out[t] = acc;
}

// Layer-2 messages over g_hr (already ReLU'd). Half-warp per edge.
__global__ __launch_bounds__(512, 1)
void msg2_kernel(const float* __restrict__ W2, float* __restrict__ out) {
    const int r    = blockIdx.x;
    const int lane = threadIdx.x & 31;
    const int warp = threadIdx.x >> 5;
    const int c    = lane & 15;
    const int half = lane >> 4;

    float Wreg[HID_C];
    const float* Wr = W2 + r * HID_C * OUT_C;
#pragma unroll
    for (int k = 0; k < HID_C; k++) Wreg[k] = Wr[k * OUT_C + c];

    const int segStart = g_off[r];
    const int segEnd   = g_off[r + 1];
    const int wg = blockIdx.y * 16 + warp;
    const int nw = gridDim.y * 16;

    for (int base = segStart + wg * 32; base < segEnd; base += nw * 32) {
        int n = segEnd - base; if (n > 32) n = 32;
        int s32 = 0, d32 = 0; float w32 = 0.0f;
        if (lane < n) {
            s32 = gs_src[base + lane];
            d32 = gs_dst[base + lane];
            w32 = gs_w[base + lane];
        }
        int nPairs = (n + 1) >> 1;
#pragma unroll 2
        for (int jj = 0; jj < nPairs; jj++) {
            int ej = jj * 2 + half;
            bool act = ej < n;
            int sel = act ? ej : 0;
            int s = __shfl_sync(0xffffffffu, s32, sel);
            int d = __shfl_sync(0xffffffffu, d32, sel);
            float wj = __shfl_sync(0xffffffffu, w32, sel);
            const float4* hr = (const float4*)(g_hr + s * HID_C);
            float a0 = 0.0f, a1 = 0.0f;
#pragma unroll
            for (int k4 = 0; k4 < HID_C / 8; k4++) {
                float4 h0 = hr[k4 * 2 + 0];
                float4 h1 = hr[k4 * 2 + 1];
                a0 += h0.x * Wreg[k4 * 8 + 0]; a0 += h0.y * Wreg[k4 * 8 + 1];
                a0 += h0.z * Wreg[k4 * 8 + 2]; a0 += h0.w * Wreg[k4 * 8 + 3];
                a1 += h1.x * Wreg[k4 * 8 + 4]; a1 += h1.y * Wreg[k4 * 8 + 5];
                a1 += h1.z * Wreg[k4 * 8 + 6]; a1 += h1.w * Wreg[k4 * 8 + 7];
            }
            if (act) atomicAdd(&out[d * OUT_C + c], (a0 + a1) * wj);
        }
    }
}

// ---------------------------------------------------------------------------
extern "C" void kernel_launch(void* const* d_in, const int* in_sizes, int n_in,
                              void* d_out, int out_size) {
    const float* x          = (const float*)d_in[0];
    const int*   edge_index = (const int*)d_in[1];
    const int*   edge_type  = (const int*)d_in[2];
    const float* W1         = (const float*)d_in[3];
    const float* root1      = (const float*)d_in[4];
    const float* b1         = (const float*)d_in[5];
    const float* W2         = (const float*)d_in[6];
    const float* root2      = (const float*)d_in[7];
    const float* b2         = (const float*)d_in[8];
    float*       out        = (float*)d_out;

    (void)in_sizes; (void)n_in; (void)out_size;

    zero_kernel<<<2048, 256>>>();                                        // 1
    count_kernel<<<(N_EDGES + 255) / 256, 256>>>(edge_index, edge_type); // 2 (+scan)
    scatter_kernel<<<(N_EDGES + SCAT_EPB - 1) / SCAT_EPB, 256>>>(edge_index); // 3
    msg1_kernel<<<dim3(N_REL, 6), 256>>>(x, W1);                         // 4 <- profiled
    root1_relu_kernel<<<(N_NODES * HID_C + 255) / 256, 256>>>(x, root1, b1); // 5
    root2_kernel<<<(N_NODES * OUT_C + 255) / 256, 256>>>(root2, b2, out);    // 6
    msg2_kernel<<<dim3(N_REL, 6), 512>>>(W2, out);                       // 7
}

// round 12
// speedup vs baseline: 2.0195x; 1.0079x over previous
#include <cuda_runtime.h>

#define N_NODES 50000
#define N_EDGES 1200000
#define N_REL   45
#define IN_C    64
#define HID_C   32
#define OUT_C   16

#define SCAT_EPB 2048   // edges per scatter block
#define XT_PAD   36     // xt/Wt row stride in floats (144B: 16B-aligned, odd/16-banks)

// Vector float2 global reduction (proven on this toolchain in r6)
#define RED2(ptr, v0, v1) \
    asm volatile("red.global.add.v2.f32 [%0], {%1, %2};" \
                 :: "l"(ptr), "f"(v0), "f"(v1) : "memory")

// Scratch (device globals: no allocation allowed in kernel_launch)
__device__ int   g_cnt[N_REL * N_NODES];   // per-(rel,dst) edge counts
__device__ int   g_hist[N_REL];            // per-relation edge counts
__device__ int   g_off[N_REL + 1];         // exclusive scan of g_hist
__device__ int   g_cursor[N_REL];          // scatter cursors
__device__ unsigned g_done;                // count_kernel completion ticket
__device__ int   g_rel[N_EDGES];           // unsorted relation per edge
__device__ int   gs_src[N_EDGES];          // sorted-by-relation edge data
__device__ int   gs_dst[N_EDGES];
__device__ float gs_w[N_EDGES];
__device__ float g_h1[N_NODES * HID_C];    // layer-1 message sums (zero-init)
__device__ float g_hr[N_NODES * HID_C];    // relu(msg + x@root1 + b1)

// ---------------------------------------------------------------------------
__global__ void zero_kernel() {
    int i = blockIdx.x * blockDim.x + threadIdx.x;
    int stride = gridDim.x * blockDim.x;
    for (; i < N_REL * N_NODES; i += stride) g_cnt[i] = 0;
    int j = blockIdx.x * blockDim.x + threadIdx.x;
    for (; j < N_NODES * HID_C; j += stride) g_h1[j] = 0.0f;
    if (blockIdx.x == 0 && threadIdx.x < N_REL) g_hist[threadIdx.x] = 0;
    if (blockIdx.x == 0 && threadIdx.x == 0) g_done = 0;
}

// counts per (rel,dst) + per-relation histogram; LAST block does the 45-bin
// exclusive scan (ticket pattern) so no separate scan launch is needed.
__global__ void count_kernel(const int* __restrict__ edge_index,
                             const int* __restrict__ edge_type) {
    __shared__ int sh[N_REL];
    if (threadIdx.x < N_REL) sh[threadIdx.x] = 0;
    __syncthreads();
    int e = blockIdx.x * blockDim.x + threadIdx.x;
    if (e < N_EDGES) {
        int dst = edge_index[N_EDGES + e];
        int rel = edge_type[e];
        g_rel[e] = rel;
        atomicAdd(&g_cnt[rel * N_NODES + dst], 1);
        atomicAdd(&sh[rel], 1);
    }
    __syncthreads();
    if (threadIdx.x < N_REL) {
        atomicAdd(&g_hist[threadIdx.x], sh[threadIdx.x]);
        __threadfence();
    }
    __syncthreads();
    if (threadIdx.x == 0) {
        unsigned t = atomicInc(&g_done, 0xffffffffu);
        if (t == gridDim.x - 1) {
            int acc = 0;
            for (int r = 0; r < N_REL; r++) {
                g_off[r] = acc;
                g_cursor[r] = acc;
                acc += g_hist[r];
            }
            g_off[N_REL] = acc;
        }
    }
}

// Hierarchical-cursor relation sort; folds mean weight 1/cnt.
__global__ __launch_bounds__(256)
void scatter_kernel(const int* __restrict__ edge_index) {
    __shared__ int sh_cnt[N_REL];
    __shared__ int sh_base[N_REL];
    const int blockStart = blockIdx.x * SCAT_EPB;

    if (threadIdx.x < N_REL) sh_cnt[threadIdx.x] = 0;
    __syncthreads();
    for (int i = threadIdx.x; i < SCAT_EPB; i += blockDim.x) {
        int e = blockStart + i;
        if (e < N_EDGES) atomicAdd(&sh_cnt[g_rel[e]], 1);
    }
    __syncthreads();
    if (threadIdx.x < N_REL) {
        sh_base[threadIdx.x] = atomicAdd(&g_cursor[threadIdx.x], sh_cnt[threadIdx.x]);
        sh_cnt[threadIdx.x] = 0;
    }
    __syncthreads();
    for (int i = threadIdx.x; i < SCAT_EPB; i += blockDim.x) {
        int e = blockStart + i;
        if (e >= N_EDGES) continue;
        int rel = g_rel[e];
        int pos = sh_base[rel] + atomicAdd(&sh_cnt[rel], 1);
        int src = edge_index[e];
        int dst = edge_index[N_EDGES + e];
        int c   = g_cnt[rel * N_NODES + dst];
        gs_src[pos] = src;
        gs_dst[pos] = dst;
        gs_w[pos]   = 1.0f / (float)(c > 0 ? c : 1);
    }
}

// ---------------------------------------------------------------------------
// Layer-1 messages: warp-level register-tiled GEMM over relation-sorted edges.
// Warp tile = 32 edges x 32 channels; thread tile = 4 edges x 8 channels.
// x staged TRANSPOSED per warp (xt[k][e], stride 36 floats): the per-k x-load
// is one LDS.128 carrying 128B of DISTINCT data (vs 16B broadcast before).
// W lives in smem (Wt[k][c]) -> no 64-reg W array -> low reg pressure.
// K processed in two 32-wide halves reusing one 32x36 staging buffer.
__global__ __launch_bounds__(256, 2)
void msg1_kernel(const float* __restrict__ x, const float* __restrict__ W1) {
    __shared__ float Wt[IN_C][XT_PAD];         // 9216B
    __shared__ float xt[8][32][XT_PAD];        // 36864B  (total 46080 < 48K)

    const int tid  = threadIdx.x;
    const int lane = tid & 31;
    const int warp = tid >> 5;     // 0..7
    const int r    = blockIdx.x;

    // stage W_r (once per block): Wt[k][c] = W1[r][k][c]
    const float* Wr = W1 + r * IN_C * HID_C;
    for (int i = tid; i < IN_C * HID_C; i += 256)
        Wt[i >> 5][i & 31] = Wr[i];
    __syncthreads();

    const int segStart = g_off[r];
    const int segEnd   = g_off[r + 1];
    const int wg = blockIdx.y * 8 + warp;
    const int nw = gridDim.y * 8;

    const int eg   = (lane & 7) * 4;   // this thread's 4 edges within the tile
    const int cg   = lane >> 3;        // this thread's channel group (8 ch)
    const int part = lane & 1;

    for (int base = segStart + wg * 32; base < segEnd; base += nw * 32) {
        int n = segEnd - base; if (n > 32) n = 32;
        int s32 = 0, d32 = 0; float w32 = 0.0f;
        if (lane < n) {
            s32 = gs_src[base + lane];
            d32 = gs_dst[base + lane];
            w32 = gs_w[base + lane];
        } else {
            s32 = gs_src[segStart];    // valid row, weight 0 -> contributes 0
        }

        float acc[4][8];
#pragma unroll
        for (int i = 0; i < 4; i++)
#pragma unroll
            for (int j = 0; j < 8; j++) acc[i][j] = 0.0f;

#pragma unroll
        for (int half = 0; half < 2; half++) {
            // stage this warp's 32 edge-rows, k-half -> transposed xt
#pragma unroll
            for (int pass = 0; pass < 2; pass++) {
                int row = (lane >> 1) + pass * 16;
                int s = __shfl_sync(0xffffffffu, s32, row);
                const float4* src4 = (const float4*)(x + (size_t)s * IN_C) + half * 8;
#pragma unroll
                for (int f = 0; f < 4; f++) {
                    float4 v = src4[part + 2 * f];
                    int kb = f * 8 + part * 4;
                    xt[warp][kb + 0][row] = v.x;
                    xt[warp][kb + 1][row] = v.y;
                    xt[warp][kb + 2][row] = v.z;
                    xt[warp][kb + 3][row] = v.w;
                }
            }
            __syncwarp();

            // 32 k-steps: 1 distinct-data x LDS + 2 multicast W LDS + 32 FFMA
#pragma unroll 8
            for (int kk = 0; kk < 32; kk++) {
                float4 xv = *(const float4*)&xt[warp][kk][eg];
                const float* wrow = &Wt[half * 32 + kk][cg * 8];
                float4 wa = *(const float4*)&wrow[0];
                float4 wb = *(const float4*)&wrow[4];
                float xc[4] = {xv.x, xv.y, xv.z, xv.w};
                float wc[8] = {wa.x, wa.y, wa.z, wa.w, wb.x, wb.y, wb.z, wb.w};
#pragma unroll
                for (int i = 0; i < 4; i++)
#pragma unroll
                    for (int j = 0; j < 8; j++)
                        acc[i][j] += xc[i] * wc[j];
            }
            __syncwarp();   // before next half overwrites xt
        }

        // epilogue: scale by 1/cnt, vector RED scatter (padded edges: w=0, d=0)
#pragma unroll
        for (int i = 0; i < 4; i++) {
            int e = eg + i;
            int d = __shfl_sync(0xffffffffu, d32, e);
            float we = __shfl_sync(0xffffffffu, w32, e);
            float* p = &g_h1[d * HID_C + cg * 8];
            RED2(p + 0, acc[i][0] * we, acc[i][1] * we);
            RED2(p + 2, acc[i][2] * we, acc[i][3] * we);
            RED2(p + 4, acc[i][4] * we, acc[i][5] * we);
            RED2(p + 6, acc[i][6] * we, acc[i][7] * we);
        }
    }
}

// ---------------------------------------------------------------------------
// g_hr[n,c] = relu(g_h1[n,c] + b1[c] + sum_i x[n,i]*root1[i,c])
__global__ void root1_relu_kernel(const float* __restrict__ x,
                                  const float* __restrict__ root,
                                  const float* __restrict__ b) {
    int t = blockIdx.x * blockDim.x + threadIdx.x;
    if (t >= N_NODES * HID_C) return;
    int n = t >> 5;
    int c = t & 31;
    float acc = b[c] + g_h1[t];
    const float4* xr = (const float4*)(x + n * IN_C);
#pragma unroll
    for (int i4 = 0; i4 < IN_C / 4; i4++) {
        float4 xv = xr[i4];
        acc += xv.x * root[(i4 * 4 + 0) * HID_C + c];
        acc += xv.y * root[(i4 * 4 + 1) * HID_C + c];
        acc += xv.z * root[(i4 * 4 + 2) * HID_C + c];
        acc += xv.w * root[(i4 * 4 + 3) * HID_C + c];
    }
    g_hr[t] = fmaxf(acc, 0.0f);
}

// out[n, c] = b2[c] + sum_i g_hr[n, i] * root2[i, c]
__global__ void root2_kernel(const float* __restrict__ root,
                             const float* __restrict__ b,
                             float* __restrict__ out) {
    int t = blockIdx.x * blockDim.x + threadIdx.x;
    if (t >= N_NODES * OUT_C) return;
    int n = t >> 4;
    int c = t & 15;
    float acc = b[c];
    const float4* hr = (const float4*)(g_hr + n * HID_C);
#pragma unroll
    for (int i4 = 0; i4 < HID_C / 4; i4++) {
        float4 hv = hr[i4];
        acc += hv.x * root[(i4 * 4 + 0) * OUT_C + c];
        acc += hv.y * root[(i4 * 4 + 1) * OUT_C + c];
        acc += hv.z * root[(i4 * 4 + 2) * OUT_C + c];
        acc += hv.w * root[(i4 * 4 + 3) * OUT_C + c];
    }
    out[t] = acc;
}

// Layer-2 messages over g_hr (already ReLU'd). Half-warp per edge.
__global__ __launch_bounds__(512, 1)
void msg2_kernel(const float* __restrict__ W2, float* __restrict__ out) {
    const int r    = blockIdx.x;
    const int lane = threadIdx.x & 31;
    const int warp = threadIdx.x >> 5;
    const int c    = lane & 15;
    const int half = lane >> 4;

    float Wreg[HID_C];
    const float* Wr = W2 + r * HID_C * OUT_C;
#pragma unroll
    for (int k = 0; k < HID_C; k++) Wreg[k] = Wr[k * OUT_C + c];

    const int segStart = g_off[r];
    const int segEnd   = g_off[r + 1];
    const int wg = blockIdx.y * 16 + warp;
    const int nw = gridDim.y * 16;

    for (int base = segStart + wg * 32; base < segEnd; base += nw * 32) {
        int n = segEnd - base; if (n > 32) n = 32;
        int s32 = 0, d32 = 0; float w32 = 0.0f;
        if (lane < n) {
            s32 = gs_src[base + lane];
            d32 = gs_dst[base + lane];
            w32 = gs_w[base + lane];
        }
        int nPairs = (n + 1) >> 1;
#pragma unroll 2
        for (int jj = 0; jj < nPairs; jj++) {
            int ej = jj * 2 + half;
            bool act = ej < n;
            int sel = act ? ej : 0;
            int s = __shfl_sync(0xffffffffu, s32, sel);
            int d = __shfl_sync(0xffffffffu, d32, sel);
            float wj = __shfl_sync(0xffffffffu, w32, sel);
            const float4* hr = (const float4*)(g_hr + s * HID_C);
            float a0 = 0.0f, a1 = 0.0f;
#pragma unroll
            for (int k4 = 0; k4 < HID_C / 8; k4++) {
                float4 h0 = hr[k4 * 2 + 0];
                float4 h1 = hr[k4 * 2 + 1];
                a0 += h0.x * Wreg[k4 * 8 + 0]; a0 += h0.y * Wreg[k4 * 8 + 1];
                a0 += h0.z * Wreg[k4 * 8 + 2]; a0 += h0.w * Wreg[k4 * 8 + 3];
                a1 += h1.x * Wreg[k4 * 8 + 4]; a1 += h1.y * Wreg[k4 * 8 + 5];
                a1 += h1.z * Wreg[k4 * 8 + 6]; a1 += h1.w * Wreg[k4 * 8 + 7];
            }
            if (act) atomicAdd(&out[d * OUT_C + c], (a0 + a1) * wj);
        }
    }
}

// ---------------------------------------------------------------------------
extern "C" void kernel_launch(void* const* d_in, const int* in_sizes, int n_in,
                              void* d_out, int out_size) {
    const float* x          = (const float*)d_in[0];
    const int*   edge_index = (const int*)d_in[1];
    const int*   edge_type  = (const int*)d_in[2];
    const float* W1         = (const float*)d_in[3];
    const float* root1      = (const float*)d_in[4];
    const float* b1         = (const float*)d_in[5];
    const float* W2         = (const float*)d_in[6];
    const float* root2      = (const float*)d_in[7];
    const float* b2         = (const float*)d_in[8];
    float*       out        = (float*)d_out;

    (void)in_sizes; (void)n_in; (void)out_size;

    zero_kernel<<<2048, 256>>>();                                        // 1
    count_kernel<<<(N_EDGES + 255) / 256, 256>>>(edge_index, edge_type); // 2 (+scan)
    scatter_kernel<<<(N_EDGES + SCAT_EPB - 1) / SCAT_EPB, 256>>>(edge_index); // 3
    msg1_kernel<<<dim3(N_REL, 6), 256>>>(x, W1);                         // 4 <- profiled
    root1_relu_kernel<<<(N_NODES * HID_C + 255) / 256, 256>>>(x, root1, b1); // 5
    root2_kernel<<<(N_NODES * OUT_C + 255) / 256, 256>>>(root2, b2, out);    // 6
    msg2_kernel<<<dim3(N_REL, 6), 512>>>(W2, out);                       // 7
}

// round 13
// speedup vs baseline: 2.1250x; 1.0522x over previous
#include <cuda_runtime.h>

#define N_NODES 50000
#define N_EDGES 1200000
#define N_REL   45
#define IN_C    64
#define HID_C   32
#define OUT_C   16

#define SCAT_EPB 2048   // edges per scatter block
#define XT_PAD   36     // xt/Wt row stride in floats (144B: 16B-aligned, odd/16-banks)

typedef unsigned long long u64;

// Vector float2 global reduction (proven in r6/r12)
#define RED2(ptr, v0, v1) \
    asm volatile("red.global.add.v2.f32 [%0], {%1, %2};" \
                 :: "l"(ptr), "f"(v0), "f"(v1) : "memory")
// Packed fp32x2 FMA: acc = a*b + acc (exact fp32 lanes)
#define FMA2(acc, a, b) \
    asm("fma.rn.f32x2 %0, %1, %2, %0;" : "+l"(acc) : "l"(a), "l"(b))
#define PACK2(out, lo, hi) \
    asm("mov.b64 %0, {%1, %2};" : "=l"(out) : "f"(lo), "f"(hi))
#define UNPACK2(lo, hi, in) \
    asm("mov.b64 {%0, %1}, %2;" : "=f"(lo), "=f"(hi) : "l"(in))

// Scratch (device globals: no allocation allowed in kernel_launch)
__device__ int   g_cnt[N_REL * N_NODES];   // per-(rel,dst) edge counts
__device__ int   g_hist[N_REL];            // per-relation edge counts
__device__ int   g_off[N_REL + 1];         // exclusive scan of g_hist
__device__ int   g_cursor[N_REL];          // scatter cursors
__device__ unsigned g_done;                // count_kernel completion ticket
__device__ int   g_rel[N_EDGES];           // unsorted relation per edge
__device__ int   gs_src[N_EDGES];          // sorted-by-relation edge data
__device__ int   gs_dst[N_EDGES];
__device__ float gs_w[N_EDGES];
__device__ float g_h1[N_NODES * HID_C];    // layer-1 message sums (zero-init)
__device__ float g_hr[N_NODES * HID_C];    // relu(msg + x@root1 + b1)

// ---------------------------------------------------------------------------
__global__ void zero_kernel() {
    int i = blockIdx.x * blockDim.x + threadIdx.x;
    int stride = gridDim.x * blockDim.x;
    for (; i < N_REL * N_NODES; i += stride) g_cnt[i] = 0;
    int j = blockIdx.x * blockDim.x + threadIdx.x;
    for (; j < N_NODES * HID_C; j += stride) g_h1[j] = 0.0f;
    if (blockIdx.x == 0 && threadIdx.x < N_REL) g_hist[threadIdx.x] = 0;
    if (blockIdx.x == 0 && threadIdx.x == 0) g_done = 0;
}

// counts per (rel,dst) + per-relation histogram; LAST block does the 45-bin
// exclusive scan (ticket pattern) so no separate scan launch is needed.
__global__ void count_kernel(const int* __restrict__ edge_index,
                             const int* __restrict__ edge_type) {
    __shared__ int sh[N_REL];
    if (threadIdx.x < N_REL) sh[threadIdx.x] = 0;
    __syncthreads();
    int e = blockIdx.x * blockDim.x + threadIdx.x;
    if (e < N_EDGES) {
        int dst = edge_index[N_EDGES + e];
        int rel = edge_type[e];
        g_rel[e] = rel;
        atomicAdd(&g_cnt[rel * N_NODES + dst], 1);
        atomicAdd(&sh[rel], 1);
    }
    __syncthreads();
    if (threadIdx.x < N_REL) {
        atomicAdd(&g_hist[threadIdx.x], sh[threadIdx.x]);
        __threadfence();
    }
    __syncthreads();
    if (threadIdx.x == 0) {
        unsigned t = atomicInc(&g_done, 0xffffffffu);
        if (t == gridDim.x - 1) {
            int acc = 0;
            for (int r = 0; r < N_REL; r++) {
                g_off[r] = acc;
                g_cursor[r] = acc;
                acc += g_hist[r];
            }
            g_off[N_REL] = acc;
        }
    }
}

// Hierarchical-cursor relation sort; folds mean weight 1/cnt.
__global__ __launch_bounds__(256)
void scatter_kernel(const int* __restrict__ edge_index) {
    __shared__ int sh_cnt[N_REL];
    __shared__ int sh_base[N_REL];
    const int blockStart = blockIdx.x * SCAT_EPB;

    if (threadIdx.x < N_REL) sh_cnt[threadIdx.x] = 0;
    __syncthreads();
    for (int i = threadIdx.x; i < SCAT_EPB; i += blockDim.x) {
        int e = blockStart + i;
        if (e < N_EDGES) atomicAdd(&sh_cnt[g_rel[e]], 1);
    }
    __syncthreads();
    if (threadIdx.x < N_REL) {
        sh_base[threadIdx.x] = atomicAdd(&g_cursor[threadIdx.x], sh_cnt[threadIdx.x]);
        sh_cnt[threadIdx.x] = 0;
    }
    __syncthreads();
    for (int i = threadIdx.x; i < SCAT_EPB; i += blockDim.x) {
        int e = blockStart + i;
        if (e >= N_EDGES) continue;
        int rel = g_rel[e];
        int pos = sh_base[rel] + atomicAdd(&sh_cnt[rel], 1);
        int src = edge_index[e];
        int dst = edge_index[N_EDGES + e];
        int c   = g_cnt[rel * N_NODES + dst];
        gs_src[pos] = src;
        gs_dst[pos] = dst;
        gs_w[pos]   = 1.0f / (float)(c > 0 ? c : 1);
    }
}

// ---------------------------------------------------------------------------
// Layer-1 messages: warp-tiled GEMM (32 edges x 32 channels per warp;
// thread = 4 edges x 8 channels) with packed f32x2 FMA over channel pairs.
// W channel-pairs come pre-packed from smem via ulonglong2 LDS; x is
// duplicated into both lanes with one mov.b64 per edge per k.
// Per kk per thread: 3 LDS + 4 pack + 16 FMA2 (was 3 LDS + 32 FFMA).
__global__ __launch_bounds__(256, 2)
void msg1_kernel(const float* __restrict__ x, const float* __restrict__ W1) {
    __shared__ float Wt[IN_C][XT_PAD];         // 9216B
    __shared__ float xt[8][32][XT_PAD];        // 36864B  (total 46080 < 48K)

    const int tid  = threadIdx.x;
    const int lane = tid & 31;
    const int warp = tid >> 5;     // 0..7
    const int r    = blockIdx.x;

    // stage W_r (once per block): Wt[k][c] = W1[r][k][c]
    const float* Wr = W1 + r * IN_C * HID_C;
    for (int i = tid; i < IN_C * HID_C; i += 256)
        Wt[i >> 5][i & 31] = Wr[i];
    __syncthreads();

    const int segStart = g_off[r];
    const int segEnd   = g_off[r + 1];
    const int wg = blockIdx.y * 8 + warp;
    const int nw = gridDim.y * 8;

    const int eg   = (lane & 7) * 4;   // this thread's 4 edges within the tile
    const int cg   = lane >> 3;        // this thread's channel group (8 ch)
    const int part = lane & 1;

    for (int base = segStart + wg * 32; base < segEnd; base += nw * 32) {
        int n = segEnd - base; if (n > 32) n = 32;
        int s32 = 0, d32 = 0; float w32 = 0.0f;
        if (lane < n) {
            s32 = gs_src[base + lane];
            d32 = gs_dst[base + lane];
            w32 = gs_w[base + lane];
        } else {
            s32 = gs_src[segStart];    // valid row, weight 0 -> contributes 0
        }

        u64 accp[4][4];
#pragma unroll
        for (int i = 0; i < 4; i++)
#pragma unroll
            for (int p = 0; p < 4; p++) accp[i][p] = 0ull;

#pragma unroll
        for (int half = 0; half < 2; half++) {
            // stage this warp's 32 edge-rows, k-half -> transposed xt
#pragma unroll
            for (int pass = 0; pass < 2; pass++) {
                int row = (lane >> 1) + pass * 16;
                int s = __shfl_sync(0xffffffffu, s32, row);
                const float4* src4 = (const float4*)(x + (size_t)s * IN_C) + half * 8;
#pragma unroll
                for (int f = 0; f < 4; f++) {
                    float4 v = src4[part + 2 * f];
                    int kb = f * 8 + part * 4;
                    xt[warp][kb + 0][row] = v.x;
                    xt[warp][kb + 1][row] = v.y;
                    xt[warp][kb + 2][row] = v.z;
                    xt[warp][kb + 3][row] = v.w;
                }
            }
            __syncwarp();

            // 32 k-steps: x LDS.128 (distinct data) + 2 W LDS.128 (pre-packed
            // channel pairs) + 4 x-dup packs + 16 f32x2 FMA
#pragma unroll 8
            for (int kk = 0; kk < 32; kk++) {
                float4 xv = *(const float4*)&xt[warp][kk][eg];
                const ulonglong2* wrow =
                    (const ulonglong2*)&Wt[half * 32 + kk][cg * 8];
                ulonglong2 wA = wrow[0];   // (w0,w1) (w2,w3)
                ulonglong2 wB = wrow[1];   // (w4,w5) (w6,w7)
                u64 xx0, xx1, xx2, xx3;
                PACK2(xx0, xv.x, xv.x);
                PACK2(xx1, xv.y, xv.y);
                PACK2(xx2, xv.z, xv.z);
                PACK2(xx3, xv.w, xv.w);
                FMA2(accp[0][0], xx0, wA.x); FMA2(accp[0][1], xx0, wA.y);
                FMA2(accp[0][2], xx0, wB.x); FMA2(accp[0][3], xx0, wB.y);
                FMA2(accp[1][0], xx1, wA.x); FMA2(accp[1][1], xx1, wA.y);
                FMA2(accp[1][2], xx1, wB.x); FMA2(accp[1][3], xx1, wB.y);
                FMA2(accp[2][0], xx2, wA.x); FMA2(accp[2][1], xx2, wA.y);
                FMA2(accp[2][2], xx2, wB.x); FMA2(accp[2][3], xx2, wB.y);
                FMA2(accp[3][0], xx3, wA.x); FMA2(accp[3][1], xx3, wA.y);
                FMA2(accp[3][2], xx3, wB.x); FMA2(accp[3][3], xx3, wB.y);
            }
            __syncwarp();   // before next half overwrites xt
        }

        // epilogue: unpack, scale by 1/cnt, vector RED scatter
#pragma unroll
        for (int i = 0; i < 4; i++) {
            int e = eg + i;
            int d = __shfl_sync(0xffffffffu, d32, e);
            float we = __shfl_sync(0xffffffffu, w32, e);
            float* p = &g_h1[d * HID_C + cg * 8];
            float v0, v1;
            UNPACK2(v0, v1, accp[i][0]); RED2(p + 0, v0 * we, v1 * we);
            UNPACK2(v0, v1, accp[i][1]); RED2(p + 2, v0 * we, v1 * we);
            UNPACK2(v0, v1, accp[i][2]); RED2(p + 4, v0 * we, v1 * we);
            UNPACK2(v0, v1, accp[i][3]); RED2(p + 6, v0 * we, v1 * we);
        }
    }
}

// ---------------------------------------------------------------------------
// g_hr[n,c] = relu(g_h1[n,c] + b1[c] + sum_i x[n,i]*root1[i,c])
__global__ void root1_relu_kernel(const float* __restrict__ x,
                                  const float* __restrict__ root,
                                  const float* __restrict__ b) {
    int t = blockIdx.x * blockDim.x + threadIdx.x;
    if (t >= N_NODES * HID_C) return;
    int n = t >> 5;
    int c = t & 31;
    float acc = b[c] + g_h1[t];
    const float4* xr = (const float4*)(x + n * IN_C);
#pragma unroll
    for (int i4 = 0; i4 < IN_C / 4; i4++) {
        float4 xv = xr[i4];
        acc += xv.x * root[(i4 * 4 + 0) * HID_C + c];
        acc += xv.y * root[(i4 * 4 + 1) * HID_C + c];
        acc += xv.z * root[(i4 * 4 + 2) * HID_C + c];
        acc += xv.w * root[(i4 * 4 + 3) * HID_C + c];
    }
    g_hr[t] = fmaxf(acc, 0.0f);
}

// out[n, c] = b2[c] + sum_i g_hr[n, i] * root2[i, c]
__global__ void root2_kernel(const float* __restrict__ root,
                             const float* __restrict__ b,
                             float* __restrict__ out) {
    int t = blockIdx.x * blockDim.x + threadIdx.x;
    if (t >= N_NODES * OUT_C) return;
    int n = t >> 4;
    int c = t & 15;
    float acc = b[c];
    const float4* hr = (const float4*)(g_hr + n * HID_C);
#pragma unroll
    for (int i4 = 0; i4 < HID_C / 4; i4++) {
        float4 hv = hr[i4];
        acc += hv.x * root[(i4 * 4 + 0) * OUT_C + c];
        acc += hv.y * root[(i4 * 4 + 1) * OUT_C + c];
        acc += hv.z * root[(i4 * 4 + 2) * OUT_C + c];
        acc += hv.w * root[(i4 * 4 + 3) * OUT_C + c];
    }
    out[t] = acc;
}

// Layer-2 messages over g_hr (already ReLU'd). Half-warp per edge.
__global__ __launch_bounds__(512, 1)
void msg2_kernel(const float* __restrict__ W2, float* __restrict__ out) {
    const int r    = blockIdx.x;
    const int lane = threadIdx.x & 31;
    const int warp = threadIdx.x >> 5;
    const int c    = lane & 15;
    const int half = lane >> 4;

    float Wreg[HID_C];
    const float* Wr = W2 + r * HID_C * OUT_C;
#pragma unroll
    for (int k = 0; k < HID_C; k++) Wreg[k] = Wr[k * OUT_C + c];

    const int segStart = g_off[r];
    const int segEnd   = g_off[r + 1];
    const int wg = blockIdx.y * 16 + warp;
    const int nw = gridDim.y * 16;

    for (int base = segStart + wg * 32; base < segEnd; base += nw * 32) {
        int n = segEnd - base; if (n > 32) n = 32;
        int s32 = 0, d32 = 0; float w32 = 0.0f;
        if (lane < n) {
            s32 = gs_src[base + lane];
            d32 = gs_dst[base + lane];
            w32 = gs_w[base + lane];
        }
        int nPairs = (n + 1) >> 1;
#pragma unroll 2
        for (int jj = 0; jj < nPairs; jj++) {
            int ej = jj * 2 + half;
            bool act = ej < n;
            int sel = act ? ej : 0;
            int s = __shfl_sync(0xffffffffu, s32, sel);
            int d = __shfl_sync(0xffffffffu, d32, sel);
            float wj = __shfl_sync(0xffffffffu, w32, sel);
            const float4* hr = (const float4*)(g_hr + s * HID_C);
            float a0 = 0.0f, a1 = 0.0f;
#pragma unroll
            for (int k4 = 0; k4 < HID_C / 8; k4++) {
                float4 h0 = hr[k4 * 2 + 0];
                float4 h1 = hr[k4 * 2 + 1];
                a0 += h0.x * Wreg[k4 * 8 + 0]; a0 += h0.y * Wreg[k4 * 8 + 1];
                a0 += h0.z * Wreg[k4 * 8 + 2]; a0 += h0.w * Wreg[k4 * 8 + 3];
                a1 += h1.x * Wreg[k4 * 8 + 4]; a1 += h1.y * Wreg[k4 * 8 + 5];
                a1 += h1.z * Wreg[k4 * 8 + 6]; a1 += h1.w * Wreg[k4 * 8 + 7];
            }
            if (act) atomicAdd(&out[d * OUT_C + c], (a0 + a1) * wj);
        }
    }
}

// ---------------------------------------------------------------------------
extern "C" void kernel_launch(void* const* d_in, const int* in_sizes, int n_in,
                              void* d_out, int out_size) {
    const float* x          = (const float*)d_in[0];
    const int*   edge_index = (const int*)d_in[1];
    const int*   edge_type  = (const int*)d_in[2];
    const float* W1         = (const float*)d_in[3];
    const float* root1      = (const float*)d_in[4];
    const float* b1         = (const float*)d_in[5];
    const float* W2         = (const float*)d_in[6];
    const float* root2      = (const float*)d_in[7];
    const float* b2         = (const float*)d_in[8];
    float*       out        = (float*)d_out;

    (void)in_sizes; (void)n_in; (void)out_size;

    zero_kernel<<<2048, 256>>>();                                        // 1
    count_kernel<<<(N_EDGES + 255) / 256, 256>>>(edge_index, edge_type); // 2 (+scan)
    scatter_kernel<<<(N_EDGES + SCAT_EPB - 1) / SCAT_EPB, 256>>>(edge_index); // 3
    msg1_kernel<<<dim3(N_REL, 6), 256>>>(x, W1);                         // 4 <- profiled
    root1_relu_kernel<<<(N_NODES * HID_C + 255) / 256, 256>>>(x, root1, b1); // 5
    root2_kernel<<<(N_NODES * OUT_C + 255) / 256, 256>>>(root2, b2, out);    // 6
    msg2_kernel<<<dim3(N_REL, 6), 512>>>(W2, out);                       // 7
}